// round 6
// baseline (speedup 1.0000x reference)
#include <cuda_runtime.h>
#include <cuda_bf16.h>
#include <math.h>
#include <stdint.h>

#define NB 8
#define TT 2048
#define DD 1024
#define MTOT (NB*TT)

#define BM 128
#define BN 256
#define BKE 32
#define STAGES 3
#define STG_BYTES 49152          // Ah 8K | Al 8K | Bh 16K | Bl 16K
#define SMEM_SZ (STAGES*STG_BYTES)

__device__ __nv_bfloat16 g_xhi[(size_t)MTOT*DD], g_xlo[(size_t)MTOT*DD];
__device__ __nv_bfloat16 g_wqhi[DD*DD], g_wqlo[DD*DD];
__device__ __nv_bfloat16 g_wkhi[DD*DD], g_wklo[DD*DD];
__device__ __nv_bfloat16 g_wvhi[DD*DD], g_wvlo[DD*DD];
__device__ __nv_bfloat16 g_qhi[(size_t)MTOT*DD], g_qlo[(size_t)MTOT*DD];
__device__ __nv_bfloat16 g_khi[(size_t)MTOT*DD], g_klo[(size_t)MTOT*DD];
__device__ __nv_bfloat16 g_vthi[(size_t)MTOT*DD], g_vtlo[(size_t)MTOT*DD];   // [DD][MTOT]
__device__ __nv_bfloat16 g_ahi[(size_t)NB*TT*TT], g_alo[(size_t)NB*TT*TT];
__device__ float g_sc[(size_t)NB*TT*TT];
__device__ float g_temp[MTOT];

// ------------------------- helpers -------------------------
__device__ __forceinline__ uint32_t smem_u32(const void* p) {
    uint32_t a;
    asm("{ .reg .u64 t; cvta.to.shared.u64 t, %1; cvt.u32.u64 %0, t; }" : "=r"(a) : "l"(p));
    return a;
}
__device__ __forceinline__ void cp16(uint32_t dst, const void* src) {
    asm volatile("cp.async.cg.shared.global [%0], [%1], 16;" :: "r"(dst), "l"(src));
}
__device__ __forceinline__ void ldsm4(uint32_t* r, uint32_t a) {
    asm volatile("ldmatrix.sync.aligned.m8n8.x4.shared.b16 {%0,%1,%2,%3}, [%4];"
                 : "=r"(r[0]), "=r"(r[1]), "=r"(r[2]), "=r"(r[3]) : "r"(a));
}
__device__ __forceinline__ void mma16816(float* c, const uint32_t* a, const uint32_t* b) {
    asm volatile("mma.sync.aligned.m16n8k16.row.col.f32.bf16.bf16.f32 "
                 "{%0,%1,%2,%3}, {%4,%5,%6,%7}, {%8,%9}, {%0,%1,%2,%3};"
                 : "+f"(c[0]), "+f"(c[1]), "+f"(c[2]), "+f"(c[3])
                 : "r"(a[0]), "r"(a[1]), "r"(a[2]), "r"(a[3]), "r"(b[0]), "r"(b[1]));
}
// 16B-chunk XOR swizzle: row r, chunk c (0..3); 64B rows
__device__ __forceinline__ uint32_t swoff(int r, int c) {
    return (uint32_t)((r * 4 + (c ^ ((r >> 1) & 3))) << 4);
}
__device__ __forceinline__ uint32_t pack2(__nv_bfloat16 a, __nv_bfloat16 b) {
    __nv_bfloat162 t(a, b);
    return *(uint32_t*)&t;
}
__device__ __forceinline__ void split1(float f, __nv_bfloat16& h, __nv_bfloat16& l) {
    h = __float2bfloat16(f);
    l = __float2bfloat16(f - __bfloat162float(h));
}

// ---------------------------------------------------------------------------
// Core bf16x3 HMMA mainloop: acc += A * B^T over K.  Tile 128x256, warp 64x64.
// ---------------------------------------------------------------------------
__device__ __forceinline__ void gemm_core(
    const __nv_bfloat16* __restrict__ Ahi, const __nv_bfloat16* __restrict__ Alo,
    const __nv_bfloat16* __restrict__ Bhi, const __nv_bfloat16* __restrict__ Blo,
    int K, int lda, int ldb, int m0, int n0,
    uint32_t sbase, int tid, float acc[4][8][4])
{
    const int lane = tid & 31, wid = tid >> 5;
    const int wm = wid >> 2, wn = wid & 3;
    const int KT = K / BKE;

    const int rA = (lane & 7) + ((lane >> 3) & 1) * 8;
    const int cA = lane >> 4;
    const int rB = (lane & 7) + ((lane >> 4) & 1) * 8;
    const int cB = (lane >> 3) & 1;

    auto load = [&](int kt) {
        const uint32_t st = sbase + (uint32_t)(kt % STAGES) * STG_BYTES;
        const int k0 = kt * BKE;
#pragma unroll
        for (int i = 0; i < 2; i++) {            // A: 512 chunk-pairs
            const int id = tid + i * 256;
            const int r = id >> 2, c = id & 3;
            const uint32_t so = swoff(r, c);
            const size_t ga = (size_t)(m0 + r) * lda + k0 + c * 8;
            cp16(st + so,        Ahi + ga);
            cp16(st + 8192 + so, Alo + ga);
        }
#pragma unroll
        for (int i = 0; i < 4; i++) {            // B: 1024 chunk-pairs
            const int id = tid + i * 256;
            const int r = id >> 2, c = id & 3;
            const uint32_t so = swoff(r, c);
            const size_t gb = (size_t)(n0 + r) * ldb + k0 + c * 8;
            cp16(st + 16384 + so, Bhi + gb);
            cp16(st + 32768 + so, Blo + gb);
        }
        asm volatile("cp.async.commit_group;");
    };

    load(0); load(1);

    for (int kt = 0; kt < KT; kt++) {
        if (kt == KT - 1) asm volatile("cp.async.wait_group 0;");
        else              asm volatile("cp.async.wait_group 1;");
        __syncthreads();
        if (kt + 2 < KT) load(kt + 2);

        const uint32_t st = sbase + (uint32_t)(kt % STAGES) * STG_BYTES;
#pragma unroll
        for (int k16 = 0; k16 < 2; k16++) {
            uint32_t bh[16], bl[16];
#pragma unroll
            for (int g2 = 0; g2 < 4; g2++) {
                const int r = wn * 64 + g2 * 16 + rB;
                const uint32_t ad = st + 16384 + swoff(r, k16 * 2 + cB);
                ldsm4(&bh[g2 * 4], ad);
                ldsm4(&bl[g2 * 4], ad + 16384);
            }
#pragma unroll
            for (int f = 0; f < 4; f++) {
                uint32_t ah[4], al[4];
                const int r = wm * 64 + f * 16 + rA;
                const uint32_t ad = st + swoff(r, k16 * 2 + cA);
                ldsm4(ah, ad);
                ldsm4(al, ad + 8192);
#pragma unroll
                for (int g = 0; g < 8; g++) {
                    mma16816(acc[f][g], ah, &bh[g * 2]);
                    mma16816(acc[f][g], ah, &bl[g * 2]);
                    mma16816(acc[f][g], al, &bh[g * 2]);
                }
            }
        }
    }
}

// ---------------------------------------------------------------------------
// Merged QKV projection: z=0 -> q (row-major), z=1 -> k (row-major),
// z=2 -> v stored transposed [e][token].
// ---------------------------------------------------------------------------
__global__ __launch_bounds__(256, 1)
void qkv_kernel(const __nv_bfloat16* __restrict__ xhi, const __nv_bfloat16* __restrict__ xlo,
                const __nv_bfloat16* __restrict__ wqh, const __nv_bfloat16* __restrict__ wql,
                const __nv_bfloat16* __restrict__ wkh, const __nv_bfloat16* __restrict__ wkl,
                const __nv_bfloat16* __restrict__ wvh, const __nv_bfloat16* __restrict__ wvl,
                __nv_bfloat16* __restrict__ qhi, __nv_bfloat16* __restrict__ qlo,
                __nv_bfloat16* __restrict__ khi, __nv_bfloat16* __restrict__ klo,
                __nv_bfloat16* __restrict__ vth, __nv_bfloat16* __restrict__ vtl)
{
    extern __shared__ char sm[];
    const uint32_t sbase = smem_u32(sm);
    const int tid = threadIdx.x, lane = tid & 31, wid = tid >> 5;
    const int wm = wid >> 2, wn = wid & 3;
    const int m0 = blockIdx.y * BM, n0 = blockIdx.x * BN, z = blockIdx.z;

    const __nv_bfloat16* Bh = (z == 0) ? wqh : (z == 1) ? wkh : wvh;
    const __nv_bfloat16* Bl = (z == 0) ? wql : (z == 1) ? wkl : wvl;

    float acc[4][8][4];
#pragma unroll
    for (int f = 0; f < 4; f++)
#pragma unroll
        for (int g = 0; g < 8; g++)
#pragma unroll
            for (int p = 0; p < 4; p++) acc[f][g][p] = 0.0f;

    gemm_core(xhi, xlo, Bh, Bl, DD, DD, DD, m0, n0, sbase, tid, acc);

    if (z < 2) {
        __nv_bfloat16* Chi = (z == 0) ? qhi : khi;
        __nv_bfloat16* Clo = (z == 0) ? qlo : klo;
#pragma unroll
        for (int f = 0; f < 4; f++) {
            const int r1 = m0 + wm * 64 + f * 16 + (lane >> 2);
            const int r2 = r1 + 8;
#pragma unroll
            for (int g = 0; g < 8; g++) {
                const int col = n0 + wn * 64 + g * 8 + (lane & 3) * 2;
                __nv_bfloat16 h0, l0, h1, l1;
                split1(acc[f][g][0], h0, l0); split1(acc[f][g][1], h1, l1);
                *(uint32_t*)(Chi + (size_t)r1 * DD + col) = pack2(h0, h1);
                *(uint32_t*)(Clo + (size_t)r1 * DD + col) = pack2(l0, l1);
                split1(acc[f][g][2], h0, l0); split1(acc[f][g][3], h1, l1);
                *(uint32_t*)(Chi + (size_t)r2 * DD + col) = pack2(h0, h1);
                *(uint32_t*)(Clo + (size_t)r2 * DD + col) = pack2(l0, l1);
            }
        }
    } else {
        // v transposed: out[e][token], ldc = MTOT
        __syncthreads();                          // stage smem reused below
        float* ws = (float*)sm + (size_t)wid * (64 * 65);   // [64][65]
#pragma unroll
        for (int f = 0; f < 4; f++)
#pragma unroll
            for (int g = 0; g < 8; g++) {
                const int mm = f * 16 + (lane >> 2);
                const int nn = g * 8 + (lane & 3) * 2;
                ws[mm * 65 + nn]           = acc[f][g][0];
                ws[mm * 65 + nn + 1]       = acc[f][g][1];
                ws[(mm + 8) * 65 + nn]     = acc[f][g][2];
                ws[(mm + 8) * 65 + nn + 1] = acc[f][g][3];
            }
        __syncwarp();
#pragma unroll
        for (int half = 0; half < 2; half++) {
            const int nloc = lane + half * 32;
            const int nrow = n0 + wn * 64 + nloc;
            uint32_t* ph = (uint32_t*)(vth + (size_t)nrow * MTOT + m0 + wm * 64);
            uint32_t* pl = (uint32_t*)(vtl + (size_t)nrow * MTOT + m0 + wm * 64);
#pragma unroll
            for (int mq = 0; mq < 32; mq++) {
                __nv_bfloat16 h0, l0, h1, l1;
                split1(ws[(2 * mq) * 65 + nloc],     h0, l0);
                split1(ws[(2 * mq + 1) * 65 + nloc], h1, l1);
                ph[mq] = pack2(h0, h1);
                pl[mq] = pack2(l0, l1);
            }
        }
    }
}

// ---------------------------------------------------------------------------
// MODE 2: C fp32 * rowscale[row]   MODE 3: C fp32
// ---------------------------------------------------------------------------
template <int MODE>
__global__ __launch_bounds__(256, 1)
void gemm3_kernel(const __nv_bfloat16* __restrict__ Ahi, const __nv_bfloat16* __restrict__ Alo,
                  const __nv_bfloat16* __restrict__ Bhi, const __nv_bfloat16* __restrict__ Blo,
                  float* __restrict__ Cf,
                  int K, int lda, int ldb, int ldc,
                  size_t sA, size_t sB, size_t sC, const float* __restrict__ rowscale)
{
    extern __shared__ char sm[];
    const uint32_t sbase = smem_u32(sm);
    const int tid = threadIdx.x, lane = tid & 31, wid = tid >> 5;
    const int wm = wid >> 2, wn = wid & 3;
    const int m0 = blockIdx.y * BM, n0 = blockIdx.x * BN, z = blockIdx.z;

    float acc[4][8][4];
#pragma unroll
    for (int f = 0; f < 4; f++)
#pragma unroll
        for (int g = 0; g < 8; g++)
#pragma unroll
            for (int p = 0; p < 4; p++) acc[f][g][p] = 0.0f;

    gemm_core(Ahi + (size_t)z * sA, Alo + (size_t)z * sA,
              Bhi + (size_t)z * sB, Blo + (size_t)z * sB,
              K, lda, ldb, m0, n0, sbase, tid, acc);

    float* C0 = Cf + (size_t)z * sC;
#pragma unroll
    for (int f = 0; f < 4; f++) {
        const int r1 = m0 + wm * 64 + f * 16 + (lane >> 2);
        const int r2 = r1 + 8;
        float s1 = 1.0f, s2 = 1.0f;
        if (MODE == 2) {
            s1 = rowscale[(size_t)z * TT + r1];
            s2 = rowscale[(size_t)z * TT + r2];
        }
#pragma unroll
        for (int g = 0; g < 8; g++) {
            const int col = n0 + wn * 64 + g * 8 + (lane & 3) * 2;
            *(float2*)(C0 + (size_t)r1 * ldc + col) = make_float2(acc[f][g][0] * s1, acc[f][g][1] * s1);
            *(float2*)(C0 + (size_t)r2 * ldc + col) = make_float2(acc[f][g][2] * s2, acc[f][g][3] * s2);
        }
    }
}

// ------------------------- aux kernels -------------------------
__global__ void split_kernel(const float* __restrict__ x, __nv_bfloat16* __restrict__ hi,
                             __nv_bfloat16* __restrict__ lo, size_t n4)
{
    size_t i = (size_t)blockIdx.x * blockDim.x + threadIdx.x;
    if (i >= n4) return;
    float4 v = ((const float4*)x)[i];
    __nv_bfloat16 h0,l0,h1,l1,h2,l2,h3,l3;
    split1(v.x,h0,l0); split1(v.y,h1,l1); split1(v.z,h2,l2); split1(v.w,h3,l3);
    ((uint2*)hi)[i] = make_uint2(pack2(h0,h1), pack2(h2,h3));
    ((uint2*)lo)[i] = make_uint2(pack2(l0,l1), pack2(l2,l3));
}

__device__ __forceinline__ float warp_sum(float v) {
#pragma unroll
    for (int o = 16; o > 0; o >>= 1) v += __shfl_xor_sync(0xffffffffu, v, o);
    return v;
}
__device__ __forceinline__ float warp_max(float v) {
#pragma unroll
    for (int o = 16; o > 0; o >>= 1) v = fmaxf(v, __shfl_xor_sync(0xffffffffu, v, o));
    return v;
}

__global__ void temp_kernel(const __nv_bfloat16* __restrict__ qhi, const __nv_bfloat16* __restrict__ qlo,
                            const float* __restrict__ hbar, float* __restrict__ temp)
{
    int row = blockIdx.x, tid = threadIdx.x;
    size_t base = (size_t)row * DD + tid * 4;
    uint2 h = *(const uint2*)(qhi + base), l = *(const uint2*)(qlo + base);
    __nv_bfloat162 h0 = *(__nv_bfloat162*)&h.x, h1 = *(__nv_bfloat162*)&h.y;
    __nv_bfloat162 l0 = *(__nv_bfloat162*)&l.x, l1 = *(__nv_bfloat162*)&l.y;
    float a = __bfloat162float(h0.x) + __bfloat162float(l0.x);
    float b = __bfloat162float(h0.y) + __bfloat162float(l0.y);
    float c = __bfloat162float(h1.x) + __bfloat162float(l1.x);
    float d = __bfloat162float(h1.y) + __bfloat162float(l1.y);
    float s = warp_sum(a*a + b*b + c*c + d*d);
    __shared__ float red[8];
    if ((tid & 31) == 0) red[tid >> 5] = s;
    __syncthreads();
    if (tid == 0) {
        float t = 0.0f;
#pragma unroll
        for (int i = 0; i < 8; i++) t += red[i];
        float tv = hbar[0] / (sqrtf(t) + 1e-8f);
        temp[row] = fminf(fmaxf(tv, 0.1f), 5.0f);
    }
}

__global__ void softmax_kernel(const float* __restrict__ sc, __nv_bfloat16* __restrict__ ahi,
                               __nv_bfloat16* __restrict__ alo)
{
    size_t row = blockIdx.x;
    const float* p = sc + row * (size_t)TT;
    int tid = threadIdx.x;
    float v[8], mx = -3.4e38f;
#pragma unroll
    for (int j = 0; j < 8; j++) { v[j] = p[tid + j * 256]; mx = fmaxf(mx, v[j]); }
    mx = warp_max(mx);
    __shared__ float red[8];
    __shared__ float bval;
    if ((tid & 31) == 0) red[tid >> 5] = mx;
    __syncthreads();
    if (tid == 0) {
        float m = red[0];
#pragma unroll
        for (int i = 1; i < 8; i++) m = fmaxf(m, red[i]);
        bval = m;
    }
    __syncthreads();
    mx = bval;
    float s = 0.0f;
#pragma unroll
    for (int j = 0; j < 8; j++) { v[j] = expf(v[j] - mx); s += v[j]; }
    s = warp_sum(s);
    __syncthreads();
    if ((tid & 31) == 0) red[tid >> 5] = s;
    __syncthreads();
    if (tid == 0) {
        float t = 0.0f;
#pragma unroll
        for (int i = 0; i < 8; i++) t += red[i];
        bval = t;
    }
    __syncthreads();
    float inv = 1.0f / bval;
#pragma unroll
    for (int j = 0; j < 8; j++) {
        __nv_bfloat16 h, l;
        split1(v[j] * inv, h, l);
        size_t idx = row * (size_t)TT + tid + j * 256;
        ahi[idx] = h;  alo[idx] = l;
    }
}

// ---------------------------------------------------------------------------
extern "C" void kernel_launch(void* const* d_in, const int* in_sizes, int n_in,
                              void* d_out, int out_size)
{
    const float* x  = (const float*)d_in[0];
    const float* Wq = (const float*)d_in[1];
    const float* Wk = (const float*)d_in[2];
    const float* Wv = (const float*)d_in[3];
    const float* hb = (const float*)d_in[4];
    float* out = (float*)d_out;

    __nv_bfloat16 *xhi,*xlo,*wqh,*wql,*wkh,*wkl,*wvh,*wvl,*qhi,*qlo,*khi,*klo,*vth,*vtl,*ahi,*alo;
    float *sc, *tmp;
    cudaGetSymbolAddress((void**)&xhi, g_xhi);  cudaGetSymbolAddress((void**)&xlo, g_xlo);
    cudaGetSymbolAddress((void**)&wqh, g_wqhi); cudaGetSymbolAddress((void**)&wql, g_wqlo);
    cudaGetSymbolAddress((void**)&wkh, g_wkhi); cudaGetSymbolAddress((void**)&wkl, g_wklo);
    cudaGetSymbolAddress((void**)&wvh, g_wvhi); cudaGetSymbolAddress((void**)&wvl, g_wvlo);
    cudaGetSymbolAddress((void**)&qhi, g_qhi);  cudaGetSymbolAddress((void**)&qlo, g_qlo);
    cudaGetSymbolAddress((void**)&khi, g_khi);  cudaGetSymbolAddress((void**)&klo, g_klo);
    cudaGetSymbolAddress((void**)&vth, g_vthi); cudaGetSymbolAddress((void**)&vtl, g_vtlo);
    cudaGetSymbolAddress((void**)&ahi, g_ahi);  cudaGetSymbolAddress((void**)&alo, g_alo);
    cudaGetSymbolAddress((void**)&sc,  g_sc);   cudaGetSymbolAddress((void**)&tmp, g_temp);

    cudaFuncSetAttribute(qkv_kernel,      cudaFuncAttributeMaxDynamicSharedMemorySize, SMEM_SZ);
    cudaFuncSetAttribute(gemm3_kernel<2>, cudaFuncAttributeMaxDynamicSharedMemorySize, SMEM_SZ);
    cudaFuncSetAttribute(gemm3_kernel<3>, cudaFuncAttributeMaxDynamicSharedMemorySize, SMEM_SZ);

    // 1) splits
    split_kernel<<<(size_t)MTOT*DD/4/256, 256>>>(x, xhi, xlo, (size_t)MTOT*DD/4);
    split_kernel<<<DD*DD/4/256, 256>>>(Wq, wqh, wql, DD*DD/4);
    split_kernel<<<DD*DD/4/256, 256>>>(Wk, wkh, wkl, DD*DD/4);
    split_kernel<<<DD*DD/4/256, 256>>>(Wv, wvh, wvl, DD*DD/4);

    // 2) merged q/k/v projections
    dim3 gq(DD/BN, MTOT/BM, 3);
    qkv_kernel<<<gq, 256, SMEM_SZ>>>(xhi, xlo, wqh, wql, wkh, wkl, wvh, wvl,
                                     qhi, qlo, khi, klo, vth, vtl);

    // 3) temp
    temp_kernel<<<MTOT, 256>>>(qhi, qlo, hb, tmp);

    // 4) scores = (q@k^T) * temp
    dim3 gs(TT/BN, TT/BM, NB);
    gemm3_kernel<2><<<gs, 256, SMEM_SZ>>>(qhi, qlo, khi, klo, sc,
                                          DD, DD, DD, TT,
                                          (size_t)TT*DD, (size_t)TT*DD, (size_t)TT*TT, tmp);

    // 5) softmax -> attn hi/lo
    softmax_kernel<<<MTOT, 256>>>(sc, ahi, alo);

    // 6) out = attn @ v
    dim3 go(DD/BN, TT/BM, NB);
    gemm3_kernel<3><<<go, 256, SMEM_SZ>>>(ahi, alo, vth, vtl, out,
                                          TT, TT, MTOT, DD,
                                          (size_t)TT*TT, TT, (size_t)TT*DD, nullptr);
}

// round 7
// speedup vs baseline: 1.1529x; 1.1529x over previous
#include <cuda_runtime.h>
#include <cuda_bf16.h>
#include <math.h>
#include <stdint.h>

#define NB 8
#define TT 2048
#define DD 1024
#define MTOT (NB*TT)

#define BM 128
#define BN 128
#define BKE 32
#define STAGES 3
#define STG_BYTES 32768          // Ah 8K | Al 8K | Bh 8K | Bl 8K
#define SMEM_SZ (STAGES*STG_BYTES)

__device__ __nv_bfloat16 g_xhi[(size_t)MTOT*DD], g_xlo[(size_t)MTOT*DD];
__device__ __nv_bfloat16 g_wqhi[DD*DD], g_wqlo[DD*DD];
__device__ __nv_bfloat16 g_wkhi[DD*DD], g_wklo[DD*DD];
__device__ __nv_bfloat16 g_wvhi[DD*DD], g_wvlo[DD*DD];
__device__ __nv_bfloat16 g_qhi[(size_t)MTOT*DD], g_qlo[(size_t)MTOT*DD];
__device__ __nv_bfloat16 g_khi[(size_t)MTOT*DD], g_klo[(size_t)MTOT*DD];
__device__ __nv_bfloat16 g_vthi[(size_t)MTOT*DD], g_vtlo[(size_t)MTOT*DD];   // [DD][MTOT]
__device__ __nv_bfloat16 g_ahi[(size_t)NB*TT*TT], g_alo[(size_t)NB*TT*TT];
__device__ float g_sc[(size_t)NB*TT*TT];
__device__ float g_temp[MTOT];

// ------------------------- helpers -------------------------
__device__ __forceinline__ uint32_t smem_u32(const void* p) {
    uint32_t a;
    asm("{ .reg .u64 t; cvta.to.shared.u64 t, %1; cvt.u32.u64 %0, t; }" : "=r"(a) : "l"(p));
    return a;
}
__device__ __forceinline__ void cp16(uint32_t dst, const void* src) {
    asm volatile("cp.async.cg.shared.global [%0], [%1], 16;" :: "r"(dst), "l"(src));
}
__device__ __forceinline__ void ldsm4(uint32_t* r, uint32_t a) {
    asm volatile("ldmatrix.sync.aligned.m8n8.x4.shared.b16 {%0,%1,%2,%3}, [%4];"
                 : "=r"(r[0]), "=r"(r[1]), "=r"(r[2]), "=r"(r[3]) : "r"(a));
}
__device__ __forceinline__ void mma16816(float* c, const uint32_t* a, const uint32_t* b) {
    asm volatile("mma.sync.aligned.m16n8k16.row.col.f32.bf16.bf16.f32 "
                 "{%0,%1,%2,%3}, {%4,%5,%6,%7}, {%8,%9}, {%0,%1,%2,%3};"
                 : "+f"(c[0]), "+f"(c[1]), "+f"(c[2]), "+f"(c[3])
                 : "r"(a[0]), "r"(a[1]), "r"(a[2]), "r"(a[3]), "r"(b[0]), "r"(b[1]));
}
// 16B-chunk XOR swizzle: row r (0..127), chunk c (0..3); 64B rows
__device__ __forceinline__ uint32_t swoff(int r, int c) {
    return (uint32_t)((r * 4 + (c ^ ((r >> 1) & 3))) << 4);
}
__device__ __forceinline__ uint32_t pack2(__nv_bfloat16 a, __nv_bfloat16 b) {
    __nv_bfloat162 t(a, b);
    return *(uint32_t*)&t;
}
__device__ __forceinline__ void split1(float f, __nv_bfloat16& h, __nv_bfloat16& l) {
    h = __float2bfloat16(f);
    l = __float2bfloat16(f - __bfloat162float(h));
}

// ---------------------------------------------------------------------------
// Core bf16x3 HMMA mainloop (R5 config): tile 128x128, warp 64x32, 3 stages.
// ---------------------------------------------------------------------------
__device__ __forceinline__ void gemm_core(
    const __nv_bfloat16* __restrict__ Ahi, const __nv_bfloat16* __restrict__ Alo,
    const __nv_bfloat16* __restrict__ Bhi, const __nv_bfloat16* __restrict__ Blo,
    int K, int lda, int ldb, int m0, int n0,
    uint32_t sbase, int tid, float acc[4][4][4])
{
    const int lane = tid & 31, wid = tid >> 5;
    const int wm = wid >> 2, wn = wid & 3;
    const int KT = K / BKE;

    const int rA = (lane & 7) + ((lane >> 3) & 1) * 8;
    const int cA = lane >> 4;
    const int rB = (lane & 7) + ((lane >> 4) & 1) * 8;
    const int cB = (lane >> 3) & 1;

    auto load = [&](int kt) {
        const uint32_t st = sbase + (uint32_t)(kt % STAGES) * STG_BYTES;
        const int k0 = kt * BKE;
#pragma unroll
        for (int i = 0; i < 2; i++) {
            const int id = tid + i * 256;             // 0..511
            const int r = id >> 2, c = id & 3;
            const uint32_t so = swoff(r, c);
            const size_t ga = (size_t)(m0 + r) * lda + k0 + c * 8;
            const size_t gb = (size_t)(n0 + r) * ldb + k0 + c * 8;
            cp16(st + so,         Ahi + ga);
            cp16(st + 8192 + so,  Alo + ga);
            cp16(st + 16384 + so, Bhi + gb);
            cp16(st + 24576 + so, Blo + gb);
        }
        asm volatile("cp.async.commit_group;");
    };

    load(0); load(1);

    for (int kt = 0; kt < KT; kt++) {
        if (kt == KT - 1) asm volatile("cp.async.wait_group 0;");
        else              asm volatile("cp.async.wait_group 1;");
        __syncthreads();
        if (kt + 2 < KT) load(kt + 2);

        const uint32_t st = sbase + (uint32_t)(kt % STAGES) * STG_BYTES;
#pragma unroll
        for (int k16 = 0; k16 < 2; k16++) {
            uint32_t bh[8], bl[8];
#pragma unroll
            for (int g2 = 0; g2 < 2; g2++) {
                const int r = wn * 32 + g2 * 16 + rB;
                const uint32_t ad = st + 16384 + swoff(r, k16 * 2 + cB);
                ldsm4(&bh[g2 * 4], ad);
                ldsm4(&bl[g2 * 4], ad + 8192);
            }
#pragma unroll
            for (int f = 0; f < 4; f++) {
                uint32_t ah[4], al[4];
                const int r = wm * 64 + f * 16 + rA;
                const uint32_t ad = st + swoff(r, k16 * 2 + cA);
                ldsm4(ah, ad);
                ldsm4(al, ad + 8192);
#pragma unroll
                for (int g = 0; g < 4; g++) {
                    mma16816(acc[f][g], ah, &bh[g * 2]);
                    mma16816(acc[f][g], ah, &bl[g * 2]);
                    mma16816(acc[f][g], al, &bh[g * 2]);
                }
            }
        }
    }
}

// ---------------------------------------------------------------------------
// Merged QKV projection (R5 tile): z=0 -> q, z=1 -> k (row-major hi/lo),
// z=2 -> v stored transposed [e][token] hi/lo.
// ---------------------------------------------------------------------------
__global__ __launch_bounds__(256, 2)
void qkv_kernel(const __nv_bfloat16* __restrict__ xhi, const __nv_bfloat16* __restrict__ xlo,
                const __nv_bfloat16* __restrict__ wqh, const __nv_bfloat16* __restrict__ wql,
                const __nv_bfloat16* __restrict__ wkh, const __nv_bfloat16* __restrict__ wkl,
                const __nv_bfloat16* __restrict__ wvh, const __nv_bfloat16* __restrict__ wvl,
                __nv_bfloat16* __restrict__ qhi, __nv_bfloat16* __restrict__ qlo,
                __nv_bfloat16* __restrict__ khi, __nv_bfloat16* __restrict__ klo,
                __nv_bfloat16* __restrict__ vth, __nv_bfloat16* __restrict__ vtl)
{
    extern __shared__ char sm[];
    const uint32_t sbase = smem_u32(sm);
    const int tid = threadIdx.x, lane = tid & 31, wid = tid >> 5;
    const int wm = wid >> 2, wn = wid & 3;
    const int m0 = blockIdx.y * BM, n0 = blockIdx.x * BN, z = blockIdx.z;

    const __nv_bfloat16* Bh = (z == 0) ? wqh : (z == 1) ? wkh : wvh;
    const __nv_bfloat16* Bl = (z == 0) ? wql : (z == 1) ? wkl : wvl;

    float acc[4][4][4];
#pragma unroll
    for (int f = 0; f < 4; f++)
#pragma unroll
        for (int g = 0; g < 4; g++)
#pragma unroll
            for (int p = 0; p < 4; p++) acc[f][g][p] = 0.0f;

    gemm_core(xhi, xlo, Bh, Bl, DD, DD, DD, m0, n0, sbase, tid, acc);

    if (z < 2) {
        __nv_bfloat16* Chi = (z == 0) ? qhi : khi;
        __nv_bfloat16* Clo = (z == 0) ? qlo : klo;
#pragma unroll
        for (int f = 0; f < 4; f++) {
            const int r1 = m0 + wm * 64 + f * 16 + (lane >> 2);
            const int r2 = r1 + 8;
#pragma unroll
            for (int g = 0; g < 4; g++) {
                const int col = n0 + wn * 32 + g * 8 + (lane & 3) * 2;
                __nv_bfloat16 h0, l0, h1, l1;
                split1(acc[f][g][0], h0, l0); split1(acc[f][g][1], h1, l1);
                *(uint32_t*)(Chi + (size_t)r1 * DD + col) = pack2(h0, h1);
                *(uint32_t*)(Clo + (size_t)r1 * DD + col) = pack2(l0, l1);
                split1(acc[f][g][2], h0, l0); split1(acc[f][g][3], h1, l1);
                *(uint32_t*)(Chi + (size_t)r2 * DD + col) = pack2(h0, h1);
                *(uint32_t*)(Clo + (size_t)r2 * DD + col) = pack2(l0, l1);
            }
        }
    } else {
        __syncthreads();    // stage buffers reused for transpose
        float* ws = (float*)(sm + wid * 8448);       // [64][33] per warp
#pragma unroll
        for (int f = 0; f < 4; f++)
#pragma unroll
            for (int g = 0; g < 4; g++) {
                const int mm = f * 16 + (lane >> 2);
                const int nn = g * 8 + (lane & 3) * 2;
                ws[mm * 33 + nn]           = acc[f][g][0];
                ws[mm * 33 + nn + 1]       = acc[f][g][1];
                ws[(mm + 8) * 33 + nn]     = acc[f][g][2];
                ws[(mm + 8) * 33 + nn + 1] = acc[f][g][3];
            }
        __syncwarp();
        const int nrow = n0 + wn * 32 + lane;
        __nv_bfloat16* ph = vth + (size_t)nrow * MTOT + m0 + wm * 64;
        __nv_bfloat16* pl = vtl + (size_t)nrow * MTOT + m0 + wm * 64;
#pragma unroll
        for (int q4 = 0; q4 < 8; q4++) {
#pragma unroll
            for (int p = 0; p < 2; p++) {
                __nv_bfloat16 h0, l0, h1, l1, h2, l2, h3, l3;
                split1(ws[(q4 * 8 + p * 4 + 0) * 33 + lane], h0, l0);
                split1(ws[(q4 * 8 + p * 4 + 1) * 33 + lane], h1, l1);
                split1(ws[(q4 * 8 + p * 4 + 2) * 33 + lane], h2, l2);
                split1(ws[(q4 * 8 + p * 4 + 3) * 33 + lane], h3, l3);
                ((uint32_t*)(ph + q4 * 8))[p * 2]     = pack2(h0, h1);
                ((uint32_t*)(ph + q4 * 8))[p * 2 + 1] = pack2(h2, h3);
                ((uint32_t*)(pl + q4 * 8))[p * 2]     = pack2(l0, l1);
                ((uint32_t*)(pl + q4 * 8))[p * 2 + 1] = pack2(l2, l3);
            }
        }
    }
}

// ---------------------------------------------------------------------------
// MODE 2: C fp32 * rowscale[row]   MODE 3: C fp32
// ---------------------------------------------------------------------------
template <int MODE>
__global__ __launch_bounds__(256, 2)
void gemm3_kernel(const __nv_bfloat16* __restrict__ Ahi, const __nv_bfloat16* __restrict__ Alo,
                  const __nv_bfloat16* __restrict__ Bhi, const __nv_bfloat16* __restrict__ Blo,
                  float* __restrict__ Cf,
                  int K, int lda, int ldb, int ldc,
                  size_t sA, size_t sB, size_t sC, const float* __restrict__ rowscale)
{
    extern __shared__ char sm[];
    const uint32_t sbase = smem_u32(sm);
    const int tid = threadIdx.x, lane = tid & 31, wid = tid >> 5;
    const int wm = wid >> 2, wn = wid & 3;
    const int m0 = blockIdx.y * BM, n0 = blockIdx.x * BN, z = blockIdx.z;

    float acc[4][4][4];
#pragma unroll
    for (int f = 0; f < 4; f++)
#pragma unroll
        for (int g = 0; g < 4; g++)
#pragma unroll
            for (int p = 0; p < 4; p++) acc[f][g][p] = 0.0f;

    gemm_core(Ahi + (size_t)z * sA, Alo + (size_t)z * sA,
              Bhi + (size_t)z * sB, Blo + (size_t)z * sB,
              K, lda, ldb, m0, n0, sbase, tid, acc);

    float* C0 = Cf + (size_t)z * sC;
#pragma unroll
    for (int f = 0; f < 4; f++) {
        const int r1 = m0 + wm * 64 + f * 16 + (lane >> 2);
        const int r2 = r1 + 8;
        float s1 = 1.0f, s2 = 1.0f;
        if (MODE == 2) {
            s1 = rowscale[(size_t)z * TT + r1];
            s2 = rowscale[(size_t)z * TT + r2];
        }
#pragma unroll
        for (int g = 0; g < 4; g++) {
            const int col = n0 + wn * 32 + g * 8 + (lane & 3) * 2;
            *(float2*)(C0 + (size_t)r1 * ldc + col) = make_float2(acc[f][g][0] * s1, acc[f][g][1] * s1);
            *(float2*)(C0 + (size_t)r2 * ldc + col) = make_float2(acc[f][g][2] * s2, acc[f][g][3] * s2);
        }
    }
}

// ------------------------- aux kernels -------------------------
__global__ void split_kernel(const float* __restrict__ x, __nv_bfloat16* __restrict__ hi,
                             __nv_bfloat16* __restrict__ lo, size_t n4)
{
    size_t i = (size_t)blockIdx.x * blockDim.x + threadIdx.x;
    if (i >= n4) return;
    float4 v = ((const float4*)x)[i];
    __nv_bfloat16 h0,l0,h1,l1,h2,l2,h3,l3;
    split1(v.x,h0,l0); split1(v.y,h1,l1); split1(v.z,h2,l2); split1(v.w,h3,l3);
    ((uint2*)hi)[i] = make_uint2(pack2(h0,h1), pack2(h2,h3));
    ((uint2*)lo)[i] = make_uint2(pack2(l0,l1), pack2(l2,l3));
}

__device__ __forceinline__ float warp_sum(float v) {
#pragma unroll
    for (int o = 16; o > 0; o >>= 1) v += __shfl_xor_sync(0xffffffffu, v, o);
    return v;
}
__device__ __forceinline__ float warp_max(float v) {
#pragma unroll
    for (int o = 16; o > 0; o >>= 1) v = fmaxf(v, __shfl_xor_sync(0xffffffffu, v, o));
    return v;
}

__global__ void temp_kernel(const __nv_bfloat16* __restrict__ qhi, const __nv_bfloat16* __restrict__ qlo,
                            const float* __restrict__ hbar, float* __restrict__ temp)
{
    int row = blockIdx.x, tid = threadIdx.x;
    size_t base = (size_t)row * DD + tid * 4;
    uint2 h = *(const uint2*)(qhi + base), l = *(const uint2*)(qlo + base);
    __nv_bfloat162 h0 = *(__nv_bfloat162*)&h.x, h1 = *(__nv_bfloat162*)&h.y;
    __nv_bfloat162 l0 = *(__nv_bfloat162*)&l.x, l1 = *(__nv_bfloat162*)&l.y;
    float a = __bfloat162float(h0.x) + __bfloat162float(l0.x);
    float b = __bfloat162float(h0.y) + __bfloat162float(l0.y);
    float c = __bfloat162float(h1.x) + __bfloat162float(l1.x);
    float d = __bfloat162float(h1.y) + __bfloat162float(l1.y);
    float s = warp_sum(a*a + b*b + c*c + d*d);
    __shared__ float red[8];
    if ((tid & 31) == 0) red[tid >> 5] = s;
    __syncthreads();
    if (tid == 0) {
        float t = 0.0f;
#pragma unroll
        for (int i = 0; i < 8; i++) t += red[i];
        float tv = hbar[0] / (sqrtf(t) + 1e-8f);
        temp[row] = fminf(fmaxf(tv, 0.1f), 5.0f);
    }
}

__global__ void softmax_kernel(const float* __restrict__ sc, __nv_bfloat16* __restrict__ ahi,
                               __nv_bfloat16* __restrict__ alo)
{
    size_t row = blockIdx.x;
    const float* p = sc + row * (size_t)TT;
    int tid = threadIdx.x;
    float v[8], mx = -3.4e38f;
#pragma unroll
    for (int j = 0; j < 8; j++) { v[j] = p[tid + j * 256]; mx = fmaxf(mx, v[j]); }
    mx = warp_max(mx);
    __shared__ float red[8];
    __shared__ float bval;
    if ((tid & 31) == 0) red[tid >> 5] = mx;
    __syncthreads();
    if (tid == 0) {
        float m = red[0];
#pragma unroll
        for (int i = 1; i < 8; i++) m = fmaxf(m, red[i]);
        bval = m;
    }
    __syncthreads();
    mx = bval;
    float s = 0.0f;
#pragma unroll
    for (int j = 0; j < 8; j++) { v[j] = __expf(v[j] - mx); s += v[j]; }
    s = warp_sum(s);
    __syncthreads();
    if ((tid & 31) == 0) red[tid >> 5] = s;
    __syncthreads();
    if (tid == 0) {
        float t = 0.0f;
#pragma unroll
        for (int i = 0; i < 8; i++) t += red[i];
        bval = t;
    }
    __syncthreads();
    float inv = 1.0f / bval;
#pragma unroll
    for (int j = 0; j < 8; j++) {
        __nv_bfloat16 h, l;
        split1(v[j] * inv, h, l);
        size_t idx = row * (size_t)TT + tid + j * 256;
        ahi[idx] = h;  alo[idx] = l;
    }
}

// ---------------------------------------------------------------------------
extern "C" void kernel_launch(void* const* d_in, const int* in_sizes, int n_in,
                              void* d_out, int out_size)
{
    const float* x  = (const float*)d_in[0];
    const float* Wq = (const float*)d_in[1];
    const float* Wk = (const float*)d_in[2];
    const float* Wv = (const float*)d_in[3];
    const float* hb = (const float*)d_in[4];
    float* out = (float*)d_out;

    __nv_bfloat16 *xhi,*xlo,*wqh,*wql,*wkh,*wkl,*wvh,*wvl,*qhi,*qlo,*khi,*klo,*vth,*vtl,*ahi,*alo;
    float *sc, *tmp;
    cudaGetSymbolAddress((void**)&xhi, g_xhi);  cudaGetSymbolAddress((void**)&xlo, g_xlo);
    cudaGetSymbolAddress((void**)&wqh, g_wqhi); cudaGetSymbolAddress((void**)&wql, g_wqlo);
    cudaGetSymbolAddress((void**)&wkh, g_wkhi); cudaGetSymbolAddress((void**)&wkl, g_wklo);
    cudaGetSymbolAddress((void**)&wvh, g_wvhi); cudaGetSymbolAddress((void**)&wvl, g_wvlo);
    cudaGetSymbolAddress((void**)&qhi, g_qhi);  cudaGetSymbolAddress((void**)&qlo, g_qlo);
    cudaGetSymbolAddress((void**)&khi, g_khi);  cudaGetSymbolAddress((void**)&klo, g_klo);
    cudaGetSymbolAddress((void**)&vth, g_vthi); cudaGetSymbolAddress((void**)&vtl, g_vtlo);
    cudaGetSymbolAddress((void**)&ahi, g_ahi);  cudaGetSymbolAddress((void**)&alo, g_alo);
    cudaGetSymbolAddress((void**)&sc,  g_sc);   cudaGetSymbolAddress((void**)&tmp, g_temp);

    cudaFuncSetAttribute(qkv_kernel,      cudaFuncAttributeMaxDynamicSharedMemorySize, SMEM_SZ);
    cudaFuncSetAttribute(gemm3_kernel<2>, cudaFuncAttributeMaxDynamicSharedMemorySize, SMEM_SZ);
    cudaFuncSetAttribute(gemm3_kernel<3>, cudaFuncAttributeMaxDynamicSharedMemorySize, SMEM_SZ);

    // 1) splits
    split_kernel<<<(size_t)MTOT*DD/4/256, 256>>>(x, xhi, xlo, (size_t)MTOT*DD/4);
    split_kernel<<<DD*DD/4/256, 256>>>(Wq, wqh, wql, DD*DD/4);
    split_kernel<<<DD*DD/4/256, 256>>>(Wk, wkh, wkl, DD*DD/4);
    split_kernel<<<DD*DD/4/256, 256>>>(Wv, wvh, wvl, DD*DD/4);

    // 2) merged q/k/v projections (R5 tile config)
    dim3 gq(DD/BN, MTOT/BM, 3);
    qkv_kernel<<<gq, 256, SMEM_SZ>>>(xhi, xlo, wqh, wql, wkh, wkl, wvh, wvl,
                                     qhi, qlo, khi, klo, vth, vtl);

    // 3) temp
    temp_kernel<<<MTOT, 256>>>(qhi, qlo, hb, tmp);

    // 4) scores = (q@k^T) * temp
    dim3 gs(TT/BN, TT/BM, NB);
    gemm3_kernel<2><<<gs, 256, SMEM_SZ>>>(qhi, qlo, khi, klo, sc,
                                          DD, DD, DD, TT,
                                          (size_t)TT*DD, (size_t)TT*DD, (size_t)TT*TT, tmp);

    // 5) softmax -> attn hi/lo
    softmax_kernel<<<MTOT, 256>>>(sc, ahi, alo);

    // 6) out = attn @ v
    dim3 go(DD/BN, TT/BM, NB);
    gemm3_kernel<3><<<go, 256, SMEM_SZ>>>(ahi, alo, vth, vtl, out,
                                          TT, TT, MTOT, DD,
                                          (size_t)TT*TT, TT, (size_t)TT*DD, nullptr);
}

// round 8
// speedup vs baseline: 1.1837x; 1.0267x over previous
#include <cuda_runtime.h>
#include <cuda_bf16.h>
#include <math.h>
#include <stdint.h>

#define NB 8
#define TT 2048
#define DD 1024
#define MTOT (NB*TT)

#define BM 128
#define BN 128
#define BKE 32
#define STAGES 3
#define STG_BYTES 32768          // Ah 8K | Al 8K | Bh 8K | Bl 8K
#define SMEM_SZ (STAGES*STG_BYTES)
#define NTHR 128

__device__ __nv_bfloat16 g_xhi[(size_t)MTOT*DD], g_xlo[(size_t)MTOT*DD];
__device__ __nv_bfloat16 g_wqhi[DD*DD], g_wqlo[DD*DD];
__device__ __nv_bfloat16 g_wkhi[DD*DD], g_wklo[DD*DD];
__device__ __nv_bfloat16 g_wvhi[DD*DD], g_wvlo[DD*DD];
__device__ __nv_bfloat16 g_qhi[(size_t)MTOT*DD], g_qlo[(size_t)MTOT*DD];
__device__ __nv_bfloat16 g_khi[(size_t)MTOT*DD], g_klo[(size_t)MTOT*DD];
__device__ __nv_bfloat16 g_vthi[(size_t)MTOT*DD], g_vtlo[(size_t)MTOT*DD];   // [DD][MTOT]
__device__ __nv_bfloat16 g_ahi[(size_t)NB*TT*TT], g_alo[(size_t)NB*TT*TT];
__device__ float g_sc[(size_t)NB*TT*TT];
__device__ float g_temp[MTOT];

// ------------------------- helpers -------------------------
__device__ __forceinline__ uint32_t smem_u32(const void* p) {
    uint32_t a;
    asm("{ .reg .u64 t; cvta.to.shared.u64 t, %1; cvt.u32.u64 %0, t; }" : "=r"(a) : "l"(p));
    return a;
}
__device__ __forceinline__ void cp16(uint32_t dst, const void* src) {
    asm volatile("cp.async.cg.shared.global [%0], [%1], 16;" :: "r"(dst), "l"(src));
}
__device__ __forceinline__ void ldsm4(uint32_t* r, uint32_t a) {
    asm volatile("ldmatrix.sync.aligned.m8n8.x4.shared.b16 {%0,%1,%2,%3}, [%4];"
                 : "=r"(r[0]), "=r"(r[1]), "=r"(r[2]), "=r"(r[3]) : "r"(a));
}
__device__ __forceinline__ void mma16816(float* c, const uint32_t* a, const uint32_t* b) {
    asm volatile("mma.sync.aligned.m16n8k16.row.col.f32.bf16.bf16.f32 "
                 "{%0,%1,%2,%3}, {%4,%5,%6,%7}, {%8,%9}, {%0,%1,%2,%3};"
                 : "+f"(c[0]), "+f"(c[1]), "+f"(c[2]), "+f"(c[3])
                 : "r"(a[0]), "r"(a[1]), "r"(a[2]), "r"(a[3]), "r"(b[0]), "r"(b[1]));
}
// 16B-chunk XOR swizzle: row r (0..127), chunk c (0..3); 64B rows
__device__ __forceinline__ uint32_t swoff(int r, int c) {
    return (uint32_t)((r * 4 + (c ^ ((r >> 1) & 3))) << 4);
}
__device__ __forceinline__ uint32_t pack2(__nv_bfloat16 a, __nv_bfloat16 b) {
    __nv_bfloat162 t(a, b);
    return *(uint32_t*)&t;
}
__device__ __forceinline__ void split1(float f, __nv_bfloat16& h, __nv_bfloat16& l) {
    h = __float2bfloat16(f);
    l = __float2bfloat16(f - __bfloat162float(h));
}

// ---------------------------------------------------------------------------
// Core bf16x3 HMMA mainloop: tile 128x128, 4 warps (2x2), warp tile 64x64,
// 128 threads, 3 stages, 2 CTAs/SM.
// ---------------------------------------------------------------------------
__device__ __forceinline__ void gemm_core(
    const __nv_bfloat16* __restrict__ Ahi, const __nv_bfloat16* __restrict__ Alo,
    const __nv_bfloat16* __restrict__ Bhi, const __nv_bfloat16* __restrict__ Blo,
    int K, int lda, int ldb, int m0, int n0,
    uint32_t sbase, int tid, float acc[4][8][4])
{
    const int lane = tid & 31, wid = tid >> 5;
    const int wm = wid >> 1, wn = wid & 1;        // 2 x 2 warp grid
    const int KT = K / BKE;

    const int rA = (lane & 7) + ((lane >> 3) & 1) * 8;
    const int cA = lane >> 4;
    const int rB = (lane & 7) + ((lane >> 4) & 1) * 8;
    const int cB = (lane >> 3) & 1;

    auto load = [&](int kt) {
        const uint32_t st = sbase + (uint32_t)(kt % STAGES) * STG_BYTES;
        const int k0 = kt * BKE;
#pragma unroll
        for (int i = 0; i < 4; i++) {
            const int id = tid + i * NTHR;            // 0..511
            const int r = id >> 2, c = id & 3;
            const uint32_t so = swoff(r, c);
            const size_t ga = (size_t)(m0 + r) * lda + k0 + c * 8;
            const size_t gb = (size_t)(n0 + r) * ldb + k0 + c * 8;
            cp16(st + so,         Ahi + ga);
            cp16(st + 8192 + so,  Alo + ga);
            cp16(st + 16384 + so, Bhi + gb);
            cp16(st + 24576 + so, Blo + gb);
        }
        asm volatile("cp.async.commit_group;");
    };

    load(0); load(1);

    for (int kt = 0; kt < KT; kt++) {
        if (kt == KT - 1) asm volatile("cp.async.wait_group 0;");
        else              asm volatile("cp.async.wait_group 1;");
        __syncthreads();
        if (kt + 2 < KT) load(kt + 2);

        const uint32_t st = sbase + (uint32_t)(kt % STAGES) * STG_BYTES;
#pragma unroll
        for (int k16 = 0; k16 < 2; k16++) {
            uint32_t bh[16], bl[16];
#pragma unroll
            for (int g2 = 0; g2 < 4; g2++) {
                const int r = wn * 64 + g2 * 16 + rB;
                const uint32_t ad = st + 16384 + swoff(r, k16 * 2 + cB);
                ldsm4(&bh[g2 * 4], ad);
                ldsm4(&bl[g2 * 4], ad + 8192);
            }
#pragma unroll
            for (int f = 0; f < 4; f++) {
                uint32_t ah[4], al[4];
                const int r = wm * 64 + f * 16 + rA;
                const uint32_t ad = st + swoff(r, k16 * 2 + cA);
                ldsm4(ah, ad);
                ldsm4(al, ad + 8192);
#pragma unroll
                for (int g = 0; g < 8; g++) {
                    mma16816(acc[f][g], ah, &bh[g * 2]);
                    mma16816(acc[f][g], ah, &bl[g * 2]);
                    mma16816(acc[f][g], al, &bh[g * 2]);
                }
            }
        }
    }
}

// ---------------------------------------------------------------------------
// Merged QKV projection: z=0 -> q, z=1 -> k (row-major hi/lo),
// z=2 -> v stored transposed [e][token] hi/lo.
// ---------------------------------------------------------------------------
__global__ __launch_bounds__(NTHR, 2)
void qkv_kernel(const __nv_bfloat16* __restrict__ xhi, const __nv_bfloat16* __restrict__ xlo,
                const __nv_bfloat16* __restrict__ wqh, const __nv_bfloat16* __restrict__ wql,
                const __nv_bfloat16* __restrict__ wkh, const __nv_bfloat16* __restrict__ wkl,
                const __nv_bfloat16* __restrict__ wvh, const __nv_bfloat16* __restrict__ wvl,
                __nv_bfloat16* __restrict__ qhi, __nv_bfloat16* __restrict__ qlo,
                __nv_bfloat16* __restrict__ khi, __nv_bfloat16* __restrict__ klo,
                __nv_bfloat16* __restrict__ vth, __nv_bfloat16* __restrict__ vtl)
{
    extern __shared__ char sm[];
    const uint32_t sbase = smem_u32(sm);
    const int tid = threadIdx.x, lane = tid & 31, wid = tid >> 5;
    const int wm = wid >> 1, wn = wid & 1;
    const int m0 = blockIdx.y * BM, n0 = blockIdx.x * BN, z = blockIdx.z;

    const __nv_bfloat16* Bh = (z == 0) ? wqh : (z == 1) ? wkh : wvh;
    const __nv_bfloat16* Bl = (z == 0) ? wql : (z == 1) ? wkl : wvl;

    float acc[4][8][4];
#pragma unroll
    for (int f = 0; f < 4; f++)
#pragma unroll
        for (int g = 0; g < 8; g++)
#pragma unroll
            for (int p = 0; p < 4; p++) acc[f][g][p] = 0.0f;

    gemm_core(xhi, xlo, Bh, Bl, DD, DD, DD, m0, n0, sbase, tid, acc);

    if (z < 2) {
        __nv_bfloat16* Chi = (z == 0) ? qhi : khi;
        __nv_bfloat16* Clo = (z == 0) ? qlo : klo;
#pragma unroll
        for (int f = 0; f < 4; f++) {
            const int r1 = m0 + wm * 64 + f * 16 + (lane >> 2);
            const int r2 = r1 + 8;
#pragma unroll
            for (int g = 0; g < 8; g++) {
                const int col = n0 + wn * 64 + g * 8 + (lane & 3) * 2;
                __nv_bfloat16 h0, l0, h1, l1;
                split1(acc[f][g][0], h0, l0); split1(acc[f][g][1], h1, l1);
                *(uint32_t*)(Chi + (size_t)r1 * DD + col) = pack2(h0, h1);
                *(uint32_t*)(Clo + (size_t)r1 * DD + col) = pack2(l0, l1);
                split1(acc[f][g][2], h0, l0); split1(acc[f][g][3], h1, l1);
                *(uint32_t*)(Chi + (size_t)r2 * DD + col) = pack2(h0, h1);
                *(uint32_t*)(Clo + (size_t)r2 * DD + col) = pack2(l0, l1);
            }
        }
    } else {
        __syncthreads();    // stage buffers reused for transpose
        float* ws = (float*)sm + (size_t)wid * (64 * 65);   // [64][65] per warp
#pragma unroll
        for (int f = 0; f < 4; f++)
#pragma unroll
            for (int g = 0; g < 8; g++) {
                const int mm = f * 16 + (lane >> 2);
                const int nn = g * 8 + (lane & 3) * 2;
                ws[mm * 65 + nn]           = acc[f][g][0];
                ws[mm * 65 + nn + 1]       = acc[f][g][1];
                ws[(mm + 8) * 65 + nn]     = acc[f][g][2];
                ws[(mm + 8) * 65 + nn + 1] = acc[f][g][3];
            }
        __syncwarp();
#pragma unroll
        for (int half = 0; half < 2; half++) {
            const int nloc = lane + half * 32;
            const int nrow = n0 + wn * 64 + nloc;
            uint32_t* ph = (uint32_t*)(vth + (size_t)nrow * MTOT + m0 + wm * 64);
            uint32_t* pl = (uint32_t*)(vtl + (size_t)nrow * MTOT + m0 + wm * 64);
#pragma unroll
            for (int mq = 0; mq < 32; mq++) {
                __nv_bfloat16 h0, l0, h1, l1;
                split1(ws[(2 * mq) * 65 + nloc],     h0, l0);
                split1(ws[(2 * mq + 1) * 65 + nloc], h1, l1);
                ph[mq] = pack2(h0, h1);
                pl[mq] = pack2(l0, l1);
            }
        }
    }
}

// ---------------------------------------------------------------------------
// MODE 2: C fp32 * rowscale[row]   MODE 3: C fp32
// ---------------------------------------------------------------------------
template <int MODE>
__global__ __launch_bounds__(NTHR, 2)
void gemm3_kernel(const __nv_bfloat16* __restrict__ Ahi, const __nv_bfloat16* __restrict__ Alo,
                  const __nv_bfloat16* __restrict__ Bhi, const __nv_bfloat16* __restrict__ Blo,
                  float* __restrict__ Cf,
                  int K, int lda, int ldb, int ldc,
                  size_t sA, size_t sB, size_t sC, const float* __restrict__ rowscale)
{
    extern __shared__ char sm[];
    const uint32_t sbase = smem_u32(sm);
    const int tid = threadIdx.x, lane = tid & 31, wid = tid >> 5;
    const int wm = wid >> 1, wn = wid & 1;
    const int m0 = blockIdx.y * BM, n0 = blockIdx.x * BN, z = blockIdx.z;

    float acc[4][8][4];
#pragma unroll
    for (int f = 0; f < 4; f++)
#pragma unroll
        for (int g = 0; g < 8; g++)
#pragma unroll
            for (int p = 0; p < 4; p++) acc[f][g][p] = 0.0f;

    gemm_core(Ahi + (size_t)z * sA, Alo + (size_t)z * sA,
              Bhi + (size_t)z * sB, Blo + (size_t)z * sB,
              K, lda, ldb, m0, n0, sbase, tid, acc);

    float* C0 = Cf + (size_t)z * sC;
#pragma unroll
    for (int f = 0; f < 4; f++) {
        const int r1 = m0 + wm * 64 + f * 16 + (lane >> 2);
        const int r2 = r1 + 8;
        float s1 = 1.0f, s2 = 1.0f;
        if (MODE == 2) {
            s1 = rowscale[(size_t)z * TT + r1];
            s2 = rowscale[(size_t)z * TT + r2];
        }
#pragma unroll
        for (int g = 0; g < 8; g++) {
            const int col = n0 + wn * 64 + g * 8 + (lane & 3) * 2;
            *(float2*)(C0 + (size_t)r1 * ldc + col) = make_float2(acc[f][g][0] * s1, acc[f][g][1] * s1);
            *(float2*)(C0 + (size_t)r2 * ldc + col) = make_float2(acc[f][g][2] * s2, acc[f][g][3] * s2);
        }
    }
}

// ------------------------- aux kernels -------------------------
__global__ void split_kernel(const float* __restrict__ x, __nv_bfloat16* __restrict__ hi,
                             __nv_bfloat16* __restrict__ lo, size_t n4)
{
    size_t i = (size_t)blockIdx.x * blockDim.x + threadIdx.x;
    if (i >= n4) return;
    float4 v = ((const float4*)x)[i];
    __nv_bfloat16 h0,l0,h1,l1,h2,l2,h3,l3;
    split1(v.x,h0,l0); split1(v.y,h1,l1); split1(v.z,h2,l2); split1(v.w,h3,l3);
    ((uint2*)hi)[i] = make_uint2(pack2(h0,h1), pack2(h2,h3));
    ((uint2*)lo)[i] = make_uint2(pack2(l0,l1), pack2(l2,l3));
}

__device__ __forceinline__ float warp_sum(float v) {
#pragma unroll
    for (int o = 16; o > 0; o >>= 1) v += __shfl_xor_sync(0xffffffffu, v, o);
    return v;
}
__device__ __forceinline__ float warp_max(float v) {
#pragma unroll
    for (int o = 16; o > 0; o >>= 1) v = fmaxf(v, __shfl_xor_sync(0xffffffffu, v, o));
    return v;
}

__global__ void temp_kernel(const __nv_bfloat16* __restrict__ qhi, const __nv_bfloat16* __restrict__ qlo,
                            const float* __restrict__ hbar, float* __restrict__ temp)
{
    int row = blockIdx.x, tid = threadIdx.x;
    size_t base = (size_t)row * DD + tid * 4;
    uint2 h = *(const uint2*)(qhi + base), l = *(const uint2*)(qlo + base);
    __nv_bfloat162 h0 = *(__nv_bfloat162*)&h.x, h1 = *(__nv_bfloat162*)&h.y;
    __nv_bfloat162 l0 = *(__nv_bfloat162*)&l.x, l1 = *(__nv_bfloat162*)&l.y;
    float a = __bfloat162float(h0.x) + __bfloat162float(l0.x);
    float b = __bfloat162float(h0.y) + __bfloat162float(l0.y);
    float c = __bfloat162float(h1.x) + __bfloat162float(l1.x);
    float d = __bfloat162float(h1.y) + __bfloat162float(l1.y);
    float s = warp_sum(a*a + b*b + c*c + d*d);
    __shared__ float red[8];
    if ((tid & 31) == 0) red[tid >> 5] = s;
    __syncthreads();
    if (tid == 0) {
        float t = 0.0f;
#pragma unroll
        for (int i = 0; i < 8; i++) t += red[i];
        float tv = hbar[0] / (sqrtf(t) + 1e-8f);
        temp[row] = fminf(fmaxf(tv, 0.1f), 5.0f);
    }
}

__global__ void softmax_kernel(const float* __restrict__ sc, __nv_bfloat16* __restrict__ ahi,
                               __nv_bfloat16* __restrict__ alo)
{
    size_t row = blockIdx.x;
    const float* p = sc + row * (size_t)TT;
    int tid = threadIdx.x;
    float v[8], mx = -3.4e38f;
#pragma unroll
    for (int j = 0; j < 8; j++) { v[j] = p[tid + j * 256]; mx = fmaxf(mx, v[j]); }
    mx = warp_max(mx);
    __shared__ float red[8];
    __shared__ float bval;
    if ((tid & 31) == 0) red[tid >> 5] = mx;
    __syncthreads();
    if (tid == 0) {
        float m = red[0];
#pragma unroll
        for (int i = 1; i < 8; i++) m = fmaxf(m, red[i]);
        bval = m;
    }
    __syncthreads();
    mx = bval;
    float s = 0.0f;
#pragma unroll
    for (int j = 0; j < 8; j++) { v[j] = __expf(v[j] - mx); s += v[j]; }
    s = warp_sum(s);
    __syncthreads();
    if ((tid & 31) == 0) red[tid >> 5] = s;
    __syncthreads();
    if (tid == 0) {
        float t = 0.0f;
#pragma unroll
        for (int i = 0; i < 8; i++) t += red[i];
        bval = t;
    }
    __syncthreads();
    float inv = 1.0f / bval;
#pragma unroll
    for (int j = 0; j < 8; j++) {
        __nv_bfloat16 h, l;
        split1(v[j] * inv, h, l);
        size_t idx = row * (size_t)TT + tid + j * 256;
        ahi[idx] = h;  alo[idx] = l;
    }
}

// ---------------------------------------------------------------------------
extern "C" void kernel_launch(void* const* d_in, const int* in_sizes, int n_in,
                              void* d_out, int out_size)
{
    const float* x  = (const float*)d_in[0];
    const float* Wq = (const float*)d_in[1];
    const float* Wk = (const float*)d_in[2];
    const float* Wv = (const float*)d_in[3];
    const float* hb = (const float*)d_in[4];
    float* out = (float*)d_out;

    __nv_bfloat16 *xhi,*xlo,*wqh,*wql,*wkh,*wkl,*wvh,*wvl,*qhi,*qlo,*khi,*klo,*vth,*vtl,*ahi,*alo;
    float *sc, *tmp;
    cudaGetSymbolAddress((void**)&xhi, g_xhi);  cudaGetSymbolAddress((void**)&xlo, g_xlo);
    cudaGetSymbolAddress((void**)&wqh, g_wqhi); cudaGetSymbolAddress((void**)&wql, g_wqlo);
    cudaGetSymbolAddress((void**)&wkh, g_wkhi); cudaGetSymbolAddress((void**)&wkl, g_wklo);
    cudaGetSymbolAddress((void**)&wvh, g_wvhi); cudaGetSymbolAddress((void**)&wvl, g_wvlo);
    cudaGetSymbolAddress((void**)&qhi, g_qhi);  cudaGetSymbolAddress((void**)&qlo, g_qlo);
    cudaGetSymbolAddress((void**)&khi, g_khi);  cudaGetSymbolAddress((void**)&klo, g_klo);
    cudaGetSymbolAddress((void**)&vth, g_vthi); cudaGetSymbolAddress((void**)&vtl, g_vtlo);
    cudaGetSymbolAddress((void**)&ahi, g_ahi);  cudaGetSymbolAddress((void**)&alo, g_alo);
    cudaGetSymbolAddress((void**)&sc,  g_sc);   cudaGetSymbolAddress((void**)&tmp, g_temp);

    cudaFuncSetAttribute(qkv_kernel,      cudaFuncAttributeMaxDynamicSharedMemorySize, SMEM_SZ);
    cudaFuncSetAttribute(gemm3_kernel<2>, cudaFuncAttributeMaxDynamicSharedMemorySize, SMEM_SZ);
    cudaFuncSetAttribute(gemm3_kernel<3>, cudaFuncAttributeMaxDynamicSharedMemorySize, SMEM_SZ);

    // 1) splits
    split_kernel<<<(size_t)MTOT*DD/4/256, 256>>>(x, xhi, xlo, (size_t)MTOT*DD/4);
    split_kernel<<<DD*DD/4/256, 256>>>(Wq, wqh, wql, DD*DD/4);
    split_kernel<<<DD*DD/4/256, 256>>>(Wk, wkh, wkl, DD*DD/4);
    split_kernel<<<DD*DD/4/256, 256>>>(Wv, wvh, wvl, DD*DD/4);

    // 2) merged q/k/v projections
    dim3 gq(DD/BN, MTOT/BM, 3);
    qkv_kernel<<<gq, NTHR, SMEM_SZ>>>(xhi, xlo, wqh, wql, wkh, wkl, wvh, wvl,
                                      qhi, qlo, khi, klo, vth, vtl);

    // 3) temp
    temp_kernel<<<MTOT, 256>>>(qhi, qlo, hb, tmp);

    // 4) scores = (q@k^T) * temp
    dim3 gs(TT/BN, TT/BM, NB);
    gemm3_kernel<2><<<gs, NTHR, SMEM_SZ>>>(qhi, qlo, khi, klo, sc,
                                           DD, DD, DD, TT,
                                           (size_t)TT*DD, (size_t)TT*DD, (size_t)TT*TT, tmp);

    // 5) softmax -> attn hi/lo
    softmax_kernel<<<MTOT, 256>>>(sc, ahi, alo);

    // 6) out = attn @ v
    dim3 go(DD/BN, TT/BM, NB);
    gemm3_kernel<3><<<go, NTHR, SMEM_SZ>>>(ahi, alo, vth, vtl, out,
                                           TT, TT, MTOT, DD,
                                           (size_t)TT*TT, TT, (size_t)TT*DD, nullptr);
}

// round 9
// speedup vs baseline: 1.2093x; 1.0216x over previous
#include <cuda_runtime.h>
#include <cuda_bf16.h>
#include <math.h>
#include <stdint.h>

#define NB 8
#define TT 2048
#define DD 1024
#define MTOT (NB*TT)

#define BM 128
#define BN 128
#define BKE 32
#define STAGES 3
#define STG_BYTES 32768          // Ah 8K | Al 8K | Bh 8K | Bl 8K
#define SMEM_SZ (STAGES*STG_BYTES)
#define NTHR 128

__device__ __nv_bfloat16 g_xhi[(size_t)MTOT*DD], g_xlo[(size_t)MTOT*DD];
__device__ __nv_bfloat16 g_wqhi[DD*DD], g_wqlo[DD*DD];
__device__ __nv_bfloat16 g_wkhi[DD*DD], g_wklo[DD*DD];
__device__ __nv_bfloat16 g_wvhi[DD*DD], g_wvlo[DD*DD];
__device__ __nv_bfloat16 g_qhi[(size_t)MTOT*DD], g_qlo[(size_t)MTOT*DD];
__device__ __nv_bfloat16 g_khi[(size_t)MTOT*DD], g_klo[(size_t)MTOT*DD];
__device__ __nv_bfloat16 g_vthi[(size_t)MTOT*DD], g_vtlo[(size_t)MTOT*DD];   // [DD][MTOT]
__device__ __nv_bfloat16 g_ahi[(size_t)NB*TT*TT], g_alo[(size_t)NB*TT*TT];
__device__ float g_sc[(size_t)NB*TT*TT];
__device__ float g_temp[MTOT];

// ------------------------- helpers -------------------------
__device__ __forceinline__ uint32_t smem_u32(const void* p) {
    uint32_t a;
    asm("{ .reg .u64 t; cvta.to.shared.u64 t, %1; cvt.u32.u64 %0, t; }" : "=r"(a) : "l"(p));
    return a;
}
__device__ __forceinline__ void cp16(uint32_t dst, const void* src) {
    asm volatile("cp.async.cg.shared.global [%0], [%1], 16;" :: "r"(dst), "l"(src));
}
__device__ __forceinline__ void ldsm4(uint32_t* r, uint32_t a) {
    asm volatile("ldmatrix.sync.aligned.m8n8.x4.shared.b16 {%0,%1,%2,%3}, [%4];"
                 : "=r"(r[0]), "=r"(r[1]), "=r"(r[2]), "=r"(r[3]) : "r"(a));
}
__device__ __forceinline__ void mma16816(float* c, const uint32_t* a, const uint32_t* b) {
    asm volatile("mma.sync.aligned.m16n8k16.row.col.f32.bf16.bf16.f32 "
                 "{%0,%1,%2,%3}, {%4,%5,%6,%7}, {%8,%9}, {%0,%1,%2,%3};"
                 : "+f"(c[0]), "+f"(c[1]), "+f"(c[2]), "+f"(c[3])
                 : "r"(a[0]), "r"(a[1]), "r"(a[2]), "r"(a[3]), "r"(b[0]), "r"(b[1]));
}
// 16B-chunk XOR swizzle: row r (0..127), chunk c (0..3); 64B rows
__device__ __forceinline__ uint32_t swoff(int r, int c) {
    return (uint32_t)((r * 4 + (c ^ ((r >> 1) & 3))) << 4);
}
__device__ __forceinline__ uint32_t pack2(__nv_bfloat16 a, __nv_bfloat16 b) {
    __nv_bfloat162 t(a, b);
    return *(uint32_t*)&t;
}
__device__ __forceinline__ void split1(float f, __nv_bfloat16& h, __nv_bfloat16& l) {
    h = __float2bfloat16(f);
    l = __float2bfloat16(f - __bfloat162float(h));
}

// ---------------------------------------------------------------------------
// Core bf16x3 HMMA mainloop: tile 128x128, 4 warps (2x2), warp tile 64x64,
// 128 threads, 3 stages, 2 CTAs/SM. Next-stage cp.async interleaved into the
// MMA stream (A-half before k16=0 MMAs, B-half before k16=1 MMAs) so the
// post-__syncthreads MIO burst overlaps tensor work.
// ---------------------------------------------------------------------------
__device__ __forceinline__ void gemm_core(
    const __nv_bfloat16* __restrict__ Ahi, const __nv_bfloat16* __restrict__ Alo,
    const __nv_bfloat16* __restrict__ Bhi, const __nv_bfloat16* __restrict__ Blo,
    int K, int lda, int ldb, int m0, int n0,
    uint32_t sbase, int tid, float acc[4][8][4])
{
    const int lane = tid & 31, wid = tid >> 5;
    const int wm = wid >> 1, wn = wid & 1;        // 2 x 2 warp grid
    const int KT = K / BKE;

    const int rA = (lane & 7) + ((lane >> 3) & 1) * 8;
    const int cA = lane >> 4;
    const int rB = (lane & 7) + ((lane >> 4) & 1) * 8;
    const int cB = (lane >> 3) & 1;

    // full-stage load (prologue only)
    auto load_full = [&](int kt) {
        const uint32_t st = sbase + (uint32_t)(kt % STAGES) * STG_BYTES;
        const int k0 = kt * BKE;
#pragma unroll
        for (int i = 0; i < 4; i++) {
            const int id = tid + i * NTHR;
            const int r = id >> 2, c = id & 3;
            const uint32_t so = swoff(r, c);
            const size_t ga = (size_t)(m0 + r) * lda + k0 + c * 8;
            const size_t gb = (size_t)(n0 + r) * ldb + k0 + c * 8;
            cp16(st + so,         Ahi + ga);
            cp16(st + 8192 + so,  Alo + ga);
            cp16(st + 16384 + so, Bhi + gb);
            cp16(st + 24576 + so, Blo + gb);
        }
        asm volatile("cp.async.commit_group;");
    };
    // half-stage loads (steady state, interleaved with MMAs)
    auto load_A = [&](int kt) {
        const uint32_t st = sbase + (uint32_t)(kt % STAGES) * STG_BYTES;
        const int k0 = kt * BKE;
#pragma unroll
        for (int i = 0; i < 4; i++) {
            const int id = tid + i * NTHR;
            const int r = id >> 2, c = id & 3;
            const uint32_t so = swoff(r, c);
            const size_t ga = (size_t)(m0 + r) * lda + k0 + c * 8;
            cp16(st + so,        Ahi + ga);
            cp16(st + 8192 + so, Alo + ga);
        }
    };
    auto load_B = [&](int kt) {
        const uint32_t st = sbase + (uint32_t)(kt % STAGES) * STG_BYTES;
        const int k0 = kt * BKE;
#pragma unroll
        for (int i = 0; i < 4; i++) {
            const int id = tid + i * NTHR;
            const int r = id >> 2, c = id & 3;
            const uint32_t so = swoff(r, c);
            const size_t gb = (size_t)(n0 + r) * ldb + k0 + c * 8;
            cp16(st + 16384 + so, Bhi + gb);
            cp16(st + 24576 + so, Blo + gb);
        }
        asm volatile("cp.async.commit_group;");
    };

    load_full(0); load_full(1);

    for (int kt = 0; kt < KT; kt++) {
        if (kt == KT - 1) asm volatile("cp.async.wait_group 0;");
        else              asm volatile("cp.async.wait_group 1;");
        __syncthreads();
        const bool more = (kt + 2 < KT);

        const uint32_t st = sbase + (uint32_t)(kt % STAGES) * STG_BYTES;
        // ---- k16 = 0 ----
        {
            uint32_t bh[16], bl[16];
#pragma unroll
            for (int g2 = 0; g2 < 4; g2++) {
                const int r = wn * 64 + g2 * 16 + rB;
                const uint32_t ad = st + 16384 + swoff(r, cB);
                ldsm4(&bh[g2 * 4], ad);
                ldsm4(&bl[g2 * 4], ad + 8192);
            }
            if (more) load_A(kt + 2);      // overlap A-half of next stage
#pragma unroll
            for (int f = 0; f < 4; f++) {
                uint32_t ah[4], al[4];
                const int r = wm * 64 + f * 16 + rA;
                const uint32_t ad = st + swoff(r, cA);
                ldsm4(ah, ad);
                ldsm4(al, ad + 8192);
#pragma unroll
                for (int g = 0; g < 8; g++) {
                    mma16816(acc[f][g], ah, &bh[g * 2]);
                    mma16816(acc[f][g], ah, &bl[g * 2]);
                    mma16816(acc[f][g], al, &bh[g * 2]);
                }
            }
        }
        // ---- k16 = 1 ----
        {
            uint32_t bh[16], bl[16];
#pragma unroll
            for (int g2 = 0; g2 < 4; g2++) {
                const int r = wn * 64 + g2 * 16 + rB;
                const uint32_t ad = st + 16384 + swoff(r, 2 + cB);
                ldsm4(&bh[g2 * 4], ad);
                ldsm4(&bl[g2 * 4], ad + 8192);
            }
            if (more) load_B(kt + 2);      // overlap B-half + commit
#pragma unroll
            for (int f = 0; f < 4; f++) {
                uint32_t ah[4], al[4];
                const int r = wm * 64 + f * 16 + rA;
                const uint32_t ad = st + swoff(r, 2 + cA);
                ldsm4(ah, ad);
                ldsm4(al, ad + 8192);
#pragma unroll
                for (int g = 0; g < 8; g++) {
                    mma16816(acc[f][g], ah, &bh[g * 2]);
                    mma16816(acc[f][g], ah, &bl[g * 2]);
                    mma16816(acc[f][g], al, &bh[g * 2]);
                }
            }
        }
    }
}

// ---------------------------------------------------------------------------
// Merged QKV projection: z=0 -> q, z=1 -> k (row-major hi/lo),
// z=2 -> v stored transposed [e][token] hi/lo.
// ---------------------------------------------------------------------------
__global__ __launch_bounds__(NTHR, 2)
void qkv_kernel(const __nv_bfloat16* __restrict__ xhi, const __nv_bfloat16* __restrict__ xlo,
                const __nv_bfloat16* __restrict__ wqh, const __nv_bfloat16* __restrict__ wql,
                const __nv_bfloat16* __restrict__ wkh, const __nv_bfloat16* __restrict__ wkl,
                const __nv_bfloat16* __restrict__ wvh, const __nv_bfloat16* __restrict__ wvl,
                __nv_bfloat16* __restrict__ qhi, __nv_bfloat16* __restrict__ qlo,
                __nv_bfloat16* __restrict__ khi, __nv_bfloat16* __restrict__ klo,
                __nv_bfloat16* __restrict__ vth, __nv_bfloat16* __restrict__ vtl)
{
    extern __shared__ char sm[];
    const uint32_t sbase = smem_u32(sm);
    const int tid = threadIdx.x, lane = tid & 31, wid = tid >> 5;
    const int wm = wid >> 1, wn = wid & 1;
    const int m0 = blockIdx.y * BM, n0 = blockIdx.x * BN, z = blockIdx.z;

    const __nv_bfloat16* Bh = (z == 0) ? wqh : (z == 1) ? wkh : wvh;
    const __nv_bfloat16* Bl = (z == 0) ? wql : (z == 1) ? wkl : wvl;

    float acc[4][8][4];
#pragma unroll
    for (int f = 0; f < 4; f++)
#pragma unroll
        for (int g = 0; g < 8; g++)
#pragma unroll
            for (int p = 0; p < 4; p++) acc[f][g][p] = 0.0f;

    gemm_core(xhi, xlo, Bh, Bl, DD, DD, DD, m0, n0, sbase, tid, acc);

    if (z < 2) {
        __nv_bfloat16* Chi = (z == 0) ? qhi : khi;
        __nv_bfloat16* Clo = (z == 0) ? qlo : klo;
#pragma unroll
        for (int f = 0; f < 4; f++) {
            const int r1 = m0 + wm * 64 + f * 16 + (lane >> 2);
            const int r2 = r1 + 8;
#pragma unroll
            for (int g = 0; g < 8; g++) {
                const int col = n0 + wn * 64 + g * 8 + (lane & 3) * 2;
                __nv_bfloat16 h0, l0, h1, l1;
                split1(acc[f][g][0], h0, l0); split1(acc[f][g][1], h1, l1);
                *(uint32_t*)(Chi + (size_t)r1 * DD + col) = pack2(h0, h1);
                *(uint32_t*)(Clo + (size_t)r1 * DD + col) = pack2(l0, l1);
                split1(acc[f][g][2], h0, l0); split1(acc[f][g][3], h1, l1);
                *(uint32_t*)(Chi + (size_t)r2 * DD + col) = pack2(h0, h1);
                *(uint32_t*)(Clo + (size_t)r2 * DD + col) = pack2(l0, l1);
            }
        }
    } else {
        __syncthreads();    // stage buffers reused for transpose
        float* ws = (float*)sm + (size_t)wid * (64 * 65);   // [64][65] per warp
#pragma unroll
        for (int f = 0; f < 4; f++)
#pragma unroll
            for (int g = 0; g < 8; g++) {
                const int mm = f * 16 + (lane >> 2);
                const int nn = g * 8 + (lane & 3) * 2;
                ws[mm * 65 + nn]           = acc[f][g][0];
                ws[mm * 65 + nn + 1]       = acc[f][g][1];
                ws[(mm + 8) * 65 + nn]     = acc[f][g][2];
                ws[(mm + 8) * 65 + nn + 1] = acc[f][g][3];
            }
        __syncwarp();
#pragma unroll
        for (int half = 0; half < 2; half++) {
            const int nloc = lane + half * 32;
            const int nrow = n0 + wn * 64 + nloc;
            uint32_t* ph = (uint32_t*)(vth + (size_t)nrow * MTOT + m0 + wm * 64);
            uint32_t* pl = (uint32_t*)(vtl + (size_t)nrow * MTOT + m0 + wm * 64);
#pragma unroll
            for (int mq = 0; mq < 32; mq++) {
                __nv_bfloat16 h0, l0, h1, l1;
                split1(ws[(2 * mq) * 65 + nloc],     h0, l0);
                split1(ws[(2 * mq + 1) * 65 + nloc], h1, l1);
                ph[mq] = pack2(h0, h1);
                pl[mq] = pack2(l0, l1);
            }
        }
    }
}

// ---------------------------------------------------------------------------
// MODE 2: C fp32 * rowscale[row]   MODE 3: C fp32
// ---------------------------------------------------------------------------
template <int MODE>
__global__ __launch_bounds__(NTHR, 2)
void gemm3_kernel(const __nv_bfloat16* __restrict__ Ahi, const __nv_bfloat16* __restrict__ Alo,
                  const __nv_bfloat16* __restrict__ Bhi, const __nv_bfloat16* __restrict__ Blo,
                  float* __restrict__ Cf,
                  int K, int lda, int ldb, int ldc,
                  size_t sA, size_t sB, size_t sC, const float* __restrict__ rowscale)
{
    extern __shared__ char sm[];
    const uint32_t sbase = smem_u32(sm);
    const int tid = threadIdx.x, lane = tid & 31, wid = tid >> 5;
    const int wm = wid >> 1, wn = wid & 1;
    const int m0 = blockIdx.y * BM, n0 = blockIdx.x * BN, z = blockIdx.z;

    float acc[4][8][4];
#pragma unroll
    for (int f = 0; f < 4; f++)
#pragma unroll
        for (int g = 0; g < 8; g++)
#pragma unroll
            for (int p = 0; p < 4; p++) acc[f][g][p] = 0.0f;

    gemm_core(Ahi + (size_t)z * sA, Alo + (size_t)z * sA,
              Bhi + (size_t)z * sB, Blo + (size_t)z * sB,
              K, lda, ldb, m0, n0, sbase, tid, acc);

    float* C0 = Cf + (size_t)z * sC;
#pragma unroll
    for (int f = 0; f < 4; f++) {
        const int r1 = m0 + wm * 64 + f * 16 + (lane >> 2);
        const int r2 = r1 + 8;
        float s1 = 1.0f, s2 = 1.0f;
        if (MODE == 2) {
            s1 = rowscale[(size_t)z * TT + r1];
            s2 = rowscale[(size_t)z * TT + r2];
        }
#pragma unroll
        for (int g = 0; g < 8; g++) {
            const int col = n0 + wn * 64 + g * 8 + (lane & 3) * 2;
            *(float2*)(C0 + (size_t)r1 * ldc + col) = make_float2(acc[f][g][0] * s1, acc[f][g][1] * s1);
            *(float2*)(C0 + (size_t)r2 * ldc + col) = make_float2(acc[f][g][2] * s2, acc[f][g][3] * s2);
        }
    }
}

// ------------------------- aux kernels -------------------------
__global__ void split_kernel(const float* __restrict__ x, __nv_bfloat16* __restrict__ hi,
                             __nv_bfloat16* __restrict__ lo, size_t n4)
{
    size_t i = (size_t)blockIdx.x * blockDim.x + threadIdx.x;
    if (i >= n4) return;
    float4 v = ((const float4*)x)[i];
    __nv_bfloat16 h0,l0,h1,l1,h2,l2,h3,l3;
    split1(v.x,h0,l0); split1(v.y,h1,l1); split1(v.z,h2,l2); split1(v.w,h3,l3);
    ((uint2*)hi)[i] = make_uint2(pack2(h0,h1), pack2(h2,h3));
    ((uint2*)lo)[i] = make_uint2(pack2(l0,l1), pack2(l2,l3));
}

__device__ __forceinline__ float warp_sum(float v) {
#pragma unroll
    for (int o = 16; o > 0; o >>= 1) v += __shfl_xor_sync(0xffffffffu, v, o);
    return v;
}
__device__ __forceinline__ float warp_max(float v) {
#pragma unroll
    for (int o = 16; o > 0; o >>= 1) v = fmaxf(v, __shfl_xor_sync(0xffffffffu, v, o));
    return v;
}

__global__ void temp_kernel(const __nv_bfloat16* __restrict__ qhi, const __nv_bfloat16* __restrict__ qlo,
                            const float* __restrict__ hbar, float* __restrict__ temp)
{
    int row = blockIdx.x, tid = threadIdx.x;
    size_t base = (size_t)row * DD + tid * 4;
    uint2 h = *(const uint2*)(qhi + base), l = *(const uint2*)(qlo + base);
    __nv_bfloat162 h0 = *(__nv_bfloat162*)&h.x, h1 = *(__nv_bfloat162*)&h.y;
    __nv_bfloat162 l0 = *(__nv_bfloat162*)&l.x, l1 = *(__nv_bfloat162*)&l.y;
    float a = __bfloat162float(h0.x) + __bfloat162float(l0.x);
    float b = __bfloat162float(h0.y) + __bfloat162float(l0.y);
    float c = __bfloat162float(h1.x) + __bfloat162float(l1.x);
    float d = __bfloat162float(h1.y) + __bfloat162float(l1.y);
    float s = warp_sum(a*a + b*b + c*c + d*d);
    __shared__ float red[8];
    if ((tid & 31) == 0) red[tid >> 5] = s;
    __syncthreads();
    if (tid == 0) {
        float t = 0.0f;
#pragma unroll
        for (int i = 0; i < 8; i++) t += red[i];
        float tv = hbar[0] / (sqrtf(t) + 1e-8f);
        temp[row] = fminf(fmaxf(tv, 0.1f), 5.0f);
    }
}

__global__ void softmax_kernel(const float* __restrict__ sc, __nv_bfloat16* __restrict__ ahi,
                               __nv_bfloat16* __restrict__ alo)
{
    size_t row = blockIdx.x;
    const float* p = sc + row * (size_t)TT;
    int tid = threadIdx.x;
    float v[8], mx = -3.4e38f;
#pragma unroll
    for (int j = 0; j < 8; j++) { v[j] = p[tid + j * 256]; mx = fmaxf(mx, v[j]); }
    mx = warp_max(mx);
    __shared__ float red[8];
    __shared__ float bval;
    if ((tid & 31) == 0) red[tid >> 5] = mx;
    __syncthreads();
    if (tid == 0) {
        float m = red[0];
#pragma unroll
        for (int i = 1; i < 8; i++) m = fmaxf(m, red[i]);
        bval = m;
    }
    __syncthreads();
    mx = bval;
    float s = 0.0f;
#pragma unroll
    for (int j = 0; j < 8; j++) { v[j] = __expf(v[j] - mx); s += v[j]; }
    s = warp_sum(s);
    __syncthreads();
    if ((tid & 31) == 0) red[tid >> 5] = s;
    __syncthreads();
    if (tid == 0) {
        float t = 0.0f;
#pragma unroll
        for (int i = 0; i < 8; i++) t += red[i];
        bval = t;
    }
    __syncthreads();
    float inv = 1.0f / bval;
#pragma unroll
    for (int j = 0; j < 8; j++) {
        __nv_bfloat16 h, l;
        split1(v[j] * inv, h, l);
        size_t idx = row * (size_t)TT + tid + j * 256;
        ahi[idx] = h;  alo[idx] = l;
    }
}

// ---------------------------------------------------------------------------
extern "C" void kernel_launch(void* const* d_in, const int* in_sizes, int n_in,
                              void* d_out, int out_size)
{
    const float* x  = (const float*)d_in[0];
    const float* Wq = (const float*)d_in[1];
    const float* Wk = (const float*)d_in[2];
    const float* Wv = (const float*)d_in[3];
    const float* hb = (const float*)d_in[4];
    float* out = (float*)d_out;

    __nv_bfloat16 *xhi,*xlo,*wqh,*wql,*wkh,*wkl,*wvh,*wvl,*qhi,*qlo,*khi,*klo,*vth,*vtl,*ahi,*alo;
    float *sc, *tmp;
    cudaGetSymbolAddress((void**)&xhi, g_xhi);  cudaGetSymbolAddress((void**)&xlo, g_xlo);
    cudaGetSymbolAddress((void**)&wqh, g_wqhi); cudaGetSymbolAddress((void**)&wql, g_wqlo);
    cudaGetSymbolAddress((void**)&wkh, g_wkhi); cudaGetSymbolAddress((void**)&wkl, g_wklo);
    cudaGetSymbolAddress((void**)&wvh, g_wvhi); cudaGetSymbolAddress((void**)&wvl, g_wvlo);
    cudaGetSymbolAddress((void**)&qhi, g_qhi);  cudaGetSymbolAddress((void**)&qlo, g_qlo);
    cudaGetSymbolAddress((void**)&khi, g_khi);  cudaGetSymbolAddress((void**)&klo, g_klo);
    cudaGetSymbolAddress((void**)&vth, g_vthi); cudaGetSymbolAddress((void**)&vtl, g_vtlo);
    cudaGetSymbolAddress((void**)&ahi, g_ahi);  cudaGetSymbolAddress((void**)&alo, g_alo);
    cudaGetSymbolAddress((void**)&sc,  g_sc);   cudaGetSymbolAddress((void**)&tmp, g_temp);

    cudaFuncSetAttribute(qkv_kernel,      cudaFuncAttributeMaxDynamicSharedMemorySize, SMEM_SZ);
    cudaFuncSetAttribute(gemm3_kernel<2>, cudaFuncAttributeMaxDynamicSharedMemorySize, SMEM_SZ);
    cudaFuncSetAttribute(gemm3_kernel<3>, cudaFuncAttributeMaxDynamicSharedMemorySize, SMEM_SZ);

    // 1) splits
    split_kernel<<<(size_t)MTOT*DD/4/256, 256>>>(x, xhi, xlo, (size_t)MTOT*DD/4);
    split_kernel<<<DD*DD/4/256, 256>>>(Wq, wqh, wql, DD*DD/4);
    split_kernel<<<DD*DD/4/256, 256>>>(Wk, wkh, wkl, DD*DD/4);
    split_kernel<<<DD*DD/4/256, 256>>>(Wv, wvh, wvl, DD*DD/4);

    // 2) merged q/k/v projections
    dim3 gq(DD/BN, MTOT/BM, 3);
    qkv_kernel<<<gq, NTHR, SMEM_SZ>>>(xhi, xlo, wqh, wql, wkh, wkl, wvh, wvl,
                                      qhi, qlo, khi, klo, vth, vtl);

    // 3) temp
    temp_kernel<<<MTOT, 256>>>(qhi, qlo, hb, tmp);

    // 4) scores = (q@k^T) * temp
    dim3 gs(TT/BN, TT/BM, NB);
    gemm3_kernel<2><<<gs, NTHR, SMEM_SZ>>>(qhi, qlo, khi, klo, sc,
                                           DD, DD, DD, TT,
                                           (size_t)TT*DD, (size_t)TT*DD, (size_t)TT*TT, tmp);

    // 5) softmax -> attn hi/lo
    softmax_kernel<<<MTOT, 256>>>(sc, ahi, alo);

    // 6) out = attn @ v
    dim3 go(DD/BN, TT/BM, NB);
    gemm3_kernel<3><<<go, NTHR, SMEM_SZ>>>(ahi, alo, vth, vtl, out,
                                           TT, TT, MTOT, DD,
                                           (size_t)TT*TT, TT, (size_t)TT*DD, nullptr);
}

// round 10
// speedup vs baseline: 1.2146x; 1.0043x over previous
#include <cuda_runtime.h>
#include <cuda_bf16.h>
#include <math.h>
#include <stdint.h>

#define NB 8
#define TT 2048
#define DD 1024
#define MTOT (NB*TT)

#define BM 128
#define BKE 32
#define STAGES 3
#define NTHR 128
// GN = warp N-tile / 8.  BN = 16*GN.  Stage bytes = 16K(A) + 2*GN*1K(B)
#define STGB(GN)  (16384 + 2*(GN)*1024)
#define SMEMSZ(GN) (STAGES*STGB(GN))

__device__ __nv_bfloat16 g_xhi[(size_t)MTOT*DD], g_xlo[(size_t)MTOT*DD];
__device__ __nv_bfloat16 g_wqhi[DD*DD], g_wqlo[DD*DD];
__device__ __nv_bfloat16 g_wkhi[DD*DD], g_wklo[DD*DD];
__device__ __nv_bfloat16 g_wvhi[DD*DD], g_wvlo[DD*DD];
__device__ __nv_bfloat16 g_qhi[(size_t)MTOT*DD], g_qlo[(size_t)MTOT*DD];
__device__ __nv_bfloat16 g_khi[(size_t)MTOT*DD], g_klo[(size_t)MTOT*DD];
__device__ __nv_bfloat16 g_vthi[(size_t)MTOT*DD], g_vtlo[(size_t)MTOT*DD];   // [DD][MTOT]
__device__ __nv_bfloat16 g_ahi[(size_t)NB*TT*TT], g_alo[(size_t)NB*TT*TT];
__device__ float g_sc[(size_t)NB*TT*TT];
__device__ float g_temp[MTOT];

// ------------------------- helpers -------------------------
__device__ __forceinline__ uint32_t smem_u32(const void* p) {
    uint32_t a;
    asm("{ .reg .u64 t; cvta.to.shared.u64 t, %1; cvt.u32.u64 %0, t; }" : "=r"(a) : "l"(p));
    return a;
}
__device__ __forceinline__ void cp16(uint32_t dst, const void* src) {
    asm volatile("cp.async.cg.shared.global [%0], [%1], 16;" :: "r"(dst), "l"(src));
}
__device__ __forceinline__ void ldsm4(uint32_t* r, uint32_t a) {
    asm volatile("ldmatrix.sync.aligned.m8n8.x4.shared.b16 {%0,%1,%2,%3}, [%4];"
                 : "=r"(r[0]), "=r"(r[1]), "=r"(r[2]), "=r"(r[3]) : "r"(a));
}
__device__ __forceinline__ void mma16816(float* c, const uint32_t* a, const uint32_t* b) {
    asm volatile("mma.sync.aligned.m16n8k16.row.col.f32.bf16.bf16.f32 "
                 "{%0,%1,%2,%3}, {%4,%5,%6,%7}, {%8,%9}, {%0,%1,%2,%3};"
                 : "+f"(c[0]), "+f"(c[1]), "+f"(c[2]), "+f"(c[3])
                 : "r"(a[0]), "r"(a[1]), "r"(a[2]), "r"(a[3]), "r"(b[0]), "r"(b[1]));
}
// 16B-chunk XOR swizzle: row r, chunk c (0..3); 64B rows
__device__ __forceinline__ uint32_t swoff(int r, int c) {
    return (uint32_t)((r * 4 + (c ^ ((r >> 1) & 3))) << 4);
}
__device__ __forceinline__ uint32_t pack2(__nv_bfloat16 a, __nv_bfloat16 b) {
    __nv_bfloat162 t(a, b);
    return *(uint32_t*)&t;
}
__device__ __forceinline__ void split1(float f, __nv_bfloat16& h, __nv_bfloat16& l) {
    h = __float2bfloat16(f);
    l = __float2bfloat16(f - __bfloat162float(h));
}

// ---------------------------------------------------------------------------
// Core bf16x3 HMMA mainloop, templated on GN (warp N-tile / 8).
// Tile BM x 16*GN, 4 warps (2x2), warp tile 64 x 8*GN, 3 stages, 2 CTAs/SM.
// Next-stage cp.async interleaved into the MMA stream.
// ---------------------------------------------------------------------------
template <int GN>
__device__ __forceinline__ void gemm_core(
    const __nv_bfloat16* __restrict__ Ahi, const __nv_bfloat16* __restrict__ Alo,
    const __nv_bfloat16* __restrict__ Bhi, const __nv_bfloat16* __restrict__ Blo,
    int K, int lda, int ldb, int m0, int n0,
    uint32_t sbase, int tid, float acc[4][GN][4])
{
    constexpr int BN_   = 16 * GN;
    constexpr int STG   = STGB(GN);
    constexpr int BLOFF = 16384 + GN * 1024;
    const int lane = tid & 31, wid = tid >> 5;
    const int wm = wid >> 1, wn = wid & 1;        // 2 x 2 warp grid
    const int KT = K / BKE;

    const int rA = (lane & 7) + ((lane >> 3) & 1) * 8;
    const int cA = lane >> 4;
    const int rB = (lane & 7) + ((lane >> 4) & 1) * 8;
    const int cB = (lane >> 3) & 1;

    auto load_A = [&](int kt, bool commit) {
        const uint32_t st = sbase + (uint32_t)(kt % STAGES) * STG;
        const int k0 = kt * BKE;
#pragma unroll
        for (int i = 0; i < 4; i++) {
            const int id = tid + i * NTHR;
            const int r = id >> 2, c = id & 3;
            const uint32_t so = swoff(r, c);
            const size_t ga = (size_t)(m0 + r) * lda + k0 + c * 8;
            cp16(st + so,        Ahi + ga);
            cp16(st + 8192 + so, Alo + ga);
        }
        if (commit) asm volatile("cp.async.commit_group;");
    };
    auto load_B = [&](int kt) {
        const uint32_t st = sbase + (uint32_t)(kt % STAGES) * STG;
        const int k0 = kt * BKE;
#pragma unroll
        for (int i = 0; i < GN / 2; i++) {
            const int id = tid + i * NTHR;
            const int r = id >> 2, c = id & 3;
            const uint32_t so = swoff(r, c);
            const size_t gb = (size_t)(n0 + r) * ldb + k0 + c * 8;
            cp16(st + 16384 + so, Bhi + gb);
            cp16(st + BLOFF + so, Blo + gb);
        }
        asm volatile("cp.async.commit_group;");
    };

    load_A(0, false); load_B(0);
    load_A(1, false); load_B(1);

    for (int kt = 0; kt < KT; kt++) {
        if (kt == KT - 1) asm volatile("cp.async.wait_group 0;");
        else              asm volatile("cp.async.wait_group 1;");
        __syncthreads();
        const bool more = (kt + 2 < KT);

        const uint32_t st = sbase + (uint32_t)(kt % STAGES) * STG;
#pragma unroll
        for (int k16 = 0; k16 < 2; k16++) {
            uint32_t bh[GN * 2], bl[GN * 2];
#pragma unroll
            for (int g2 = 0; g2 < GN / 2; g2++) {
                const int r = wn * (GN * 8) + g2 * 16 + rB;
                const uint32_t ad = st + 16384 + swoff(r, k16 * 2 + cB);
                ldsm4(&bh[g2 * 4], ad);
                ldsm4(&bl[g2 * 4], ad + GN * 1024);
            }
            if (more) {
                if (k16 == 0) load_A(kt + 2, false);   // overlap with MMAs
                else          load_B(kt + 2);          // + commit
            }
#pragma unroll
            for (int f = 0; f < 4; f++) {
                uint32_t ah[4], al[4];
                const int r = wm * 64 + f * 16 + rA;
                const uint32_t ad = st + swoff(r, k16 * 2 + cA);
                ldsm4(ah, ad);
                ldsm4(al, ad + 8192);
#pragma unroll
                for (int g = 0; g < GN; g++) {
                    mma16816(acc[f][g], ah, &bh[g * 2]);
                    mma16816(acc[f][g], ah, &bl[g * 2]);
                    mma16816(acc[f][g], al, &bh[g * 2]);
                }
            }
        }
    }
}

// ---------------------------------------------------------------------------
// Merged QKV projection (GN=8): z=0 -> q, z=1 -> k (row-major hi/lo),
// z=2 -> v stored transposed [e][token] hi/lo.
// ---------------------------------------------------------------------------
__global__ __launch_bounds__(NTHR, 2)
void qkv_kernel(const __nv_bfloat16* __restrict__ xhi, const __nv_bfloat16* __restrict__ xlo,
                const __nv_bfloat16* __restrict__ wqh, const __nv_bfloat16* __restrict__ wql,
                const __nv_bfloat16* __restrict__ wkh, const __nv_bfloat16* __restrict__ wkl,
                const __nv_bfloat16* __restrict__ wvh, const __nv_bfloat16* __restrict__ wvl,
                __nv_bfloat16* __restrict__ qhi, __nv_bfloat16* __restrict__ qlo,
                __nv_bfloat16* __restrict__ khi, __nv_bfloat16* __restrict__ klo,
                __nv_bfloat16* __restrict__ vth, __nv_bfloat16* __restrict__ vtl)
{
    extern __shared__ char sm[];
    const uint32_t sbase = smem_u32(sm);
    const int tid = threadIdx.x, lane = tid & 31, wid = tid >> 5;
    const int wm = wid >> 1, wn = wid & 1;
    const int m0 = blockIdx.y * BM, n0 = blockIdx.x * 128, z = blockIdx.z;

    const __nv_bfloat16* Bh = (z == 0) ? wqh : (z == 1) ? wkh : wvh;
    const __nv_bfloat16* Bl = (z == 0) ? wql : (z == 1) ? wkl : wvl;

    float acc[4][8][4];
#pragma unroll
    for (int f = 0; f < 4; f++)
#pragma unroll
        for (int g = 0; g < 8; g++)
#pragma unroll
            for (int p = 0; p < 4; p++) acc[f][g][p] = 0.0f;

    gemm_core<8>(xhi, xlo, Bh, Bl, DD, DD, DD, m0, n0, sbase, tid, acc);

    if (z < 2) {
        __nv_bfloat16* Chi = (z == 0) ? qhi : khi;
        __nv_bfloat16* Clo = (z == 0) ? qlo : klo;
#pragma unroll
        for (int f = 0; f < 4; f++) {
            const int r1 = m0 + wm * 64 + f * 16 + (lane >> 2);
            const int r2 = r1 + 8;
#pragma unroll
            for (int g = 0; g < 8; g++) {
                const int col = n0 + wn * 64 + g * 8 + (lane & 3) * 2;
                __nv_bfloat16 h0, l0, h1, l1;
                split1(acc[f][g][0], h0, l0); split1(acc[f][g][1], h1, l1);
                *(uint32_t*)(Chi + (size_t)r1 * DD + col) = pack2(h0, h1);
                *(uint32_t*)(Clo + (size_t)r1 * DD + col) = pack2(l0, l1);
                split1(acc[f][g][2], h0, l0); split1(acc[f][g][3], h1, l1);
                *(uint32_t*)(Chi + (size_t)r2 * DD + col) = pack2(h0, h1);
                *(uint32_t*)(Clo + (size_t)r2 * DD + col) = pack2(l0, l1);
            }
        }
    } else {
        __syncthreads();    // stage buffers reused for transpose
        float* ws = (float*)sm + (size_t)wid * (64 * 65);   // [64][65] per warp
#pragma unroll
        for (int f = 0; f < 4; f++)
#pragma unroll
            for (int g = 0; g < 8; g++) {
                const int mm = f * 16 + (lane >> 2);
                const int nn = g * 8 + (lane & 3) * 2;
                ws[mm * 65 + nn]           = acc[f][g][0];
                ws[mm * 65 + nn + 1]       = acc[f][g][1];
                ws[(mm + 8) * 65 + nn]     = acc[f][g][2];
                ws[(mm + 8) * 65 + nn + 1] = acc[f][g][3];
            }
        __syncwarp();
#pragma unroll
        for (int half = 0; half < 2; half++) {
            const int nloc = lane + half * 32;
            const int nrow = n0 + wn * 64 + nloc;
            uint32_t* ph = (uint32_t*)(vth + (size_t)nrow * MTOT + m0 + wm * 64);
            uint32_t* pl = (uint32_t*)(vtl + (size_t)nrow * MTOT + m0 + wm * 64);
#pragma unroll
            for (int mq = 0; mq < 32; mq++) {
                __nv_bfloat16 h0, l0, h1, l1;
                split1(ws[(2 * mq) * 65 + nloc],     h0, l0);
                split1(ws[(2 * mq + 1) * 65 + nloc], h1, l1);
                ph[mq] = pack2(h0, h1);
                pl[mq] = pack2(l0, l1);
            }
        }
    }
}

// ---------------------------------------------------------------------------
// MODE 2: C fp32 * rowscale[row] (GN=8)   MODE 3: C fp32 (GN=4, BN=64)
// ---------------------------------------------------------------------------
template <int MODE, int GN>
__global__ __launch_bounds__(NTHR, 2)
void gemm3_kernel(const __nv_bfloat16* __restrict__ Ahi, const __nv_bfloat16* __restrict__ Alo,
                  const __nv_bfloat16* __restrict__ Bhi, const __nv_bfloat16* __restrict__ Blo,
                  float* __restrict__ Cf,
                  int K, int lda, int ldb, int ldc,
                  size_t sA, size_t sB, size_t sC, const float* __restrict__ rowscale)
{
    extern __shared__ char sm[];
    const uint32_t sbase = smem_u32(sm);
    const int tid = threadIdx.x, lane = tid & 31, wid = tid >> 5;
    const int wm = wid >> 1, wn = wid & 1;
    const int m0 = blockIdx.y * BM, n0 = blockIdx.x * (16 * GN), z = blockIdx.z;

    float acc[4][GN][4];
#pragma unroll
    for (int f = 0; f < 4; f++)
#pragma unroll
        for (int g = 0; g < GN; g++)
#pragma unroll
            for (int p = 0; p < 4; p++) acc[f][g][p] = 0.0f;

    gemm_core<GN>(Ahi + (size_t)z * sA, Alo + (size_t)z * sA,
                  Bhi + (size_t)z * sB, Blo + (size_t)z * sB,
                  K, lda, ldb, m0, n0, sbase, tid, acc);

    float* C0 = Cf + (size_t)z * sC;
#pragma unroll
    for (int f = 0; f < 4; f++) {
        const int r1 = m0 + wm * 64 + f * 16 + (lane >> 2);
        const int r2 = r1 + 8;
        float s1 = 1.0f, s2 = 1.0f;
        if (MODE == 2) {
            s1 = rowscale[(size_t)z * TT + r1];
            s2 = rowscale[(size_t)z * TT + r2];
        }
#pragma unroll
        for (int g = 0; g < GN; g++) {
            const int col = n0 + wn * (GN * 8) + g * 8 + (lane & 3) * 2;
            *(float2*)(C0 + (size_t)r1 * ldc + col) = make_float2(acc[f][g][0] * s1, acc[f][g][1] * s1);
            *(float2*)(C0 + (size_t)r2 * ldc + col) = make_float2(acc[f][g][2] * s2, acc[f][g][3] * s2);
        }
    }
}

// ------------------------- aux kernels -------------------------
__global__ void split_kernel(const float* __restrict__ x, __nv_bfloat16* __restrict__ hi,
                             __nv_bfloat16* __restrict__ lo, size_t n4)
{
    size_t i = (size_t)blockIdx.x * blockDim.x + threadIdx.x;
    if (i >= n4) return;
    float4 v = ((const float4*)x)[i];
    __nv_bfloat16 h0,l0,h1,l1,h2,l2,h3,l3;
    split1(v.x,h0,l0); split1(v.y,h1,l1); split1(v.z,h2,l2); split1(v.w,h3,l3);
    ((uint2*)hi)[i] = make_uint2(pack2(h0,h1), pack2(h2,h3));
    ((uint2*)lo)[i] = make_uint2(pack2(l0,l1), pack2(l2,l3));
}

// merged 3-weight split: blockIdx.y selects which W
__global__ void splitW_kernel(const float* __restrict__ Wq, const float* __restrict__ Wk,
                              const float* __restrict__ Wv,
                              __nv_bfloat16* __restrict__ qh, __nv_bfloat16* __restrict__ ql,
                              __nv_bfloat16* __restrict__ kh, __nv_bfloat16* __restrict__ kl,
                              __nv_bfloat16* __restrict__ vh, __nv_bfloat16* __restrict__ vl)
{
    const int z = blockIdx.y;
    const float* src = (z == 0) ? Wq : (z == 1) ? Wk : Wv;
    __nv_bfloat16* hi = (z == 0) ? qh : (z == 1) ? kh : vh;
    __nv_bfloat16* lo = (z == 0) ? ql : (z == 1) ? kl : vl;
    size_t i = (size_t)blockIdx.x * blockDim.x + threadIdx.x;
    float4 v = ((const float4*)src)[i];
    __nv_bfloat16 h0,l0,h1,l1,h2,l2,h3,l3;
    split1(v.x,h0,l0); split1(v.y,h1,l1); split1(v.z,h2,l2); split1(v.w,h3,l3);
    ((uint2*)hi)[i] = make_uint2(pack2(h0,h1), pack2(h2,h3));
    ((uint2*)lo)[i] = make_uint2(pack2(l0,l1), pack2(l2,l3));
}

__device__ __forceinline__ float warp_sum(float v) {
#pragma unroll
    for (int o = 16; o > 0; o >>= 1) v += __shfl_xor_sync(0xffffffffu, v, o);
    return v;
}
__device__ __forceinline__ float warp_max(float v) {
#pragma unroll
    for (int o = 16; o > 0; o >>= 1) v = fmaxf(v, __shfl_xor_sync(0xffffffffu, v, o));
    return v;
}

__global__ void temp_kernel(const __nv_bfloat16* __restrict__ qhi, const __nv_bfloat16* __restrict__ qlo,
                            const float* __restrict__ hbar, float* __restrict__ temp)
{
    int row = blockIdx.x, tid = threadIdx.x;
    size_t base = (size_t)row * DD + tid * 4;
    uint2 h = *(const uint2*)(qhi + base), l = *(const uint2*)(qlo + base);
    __nv_bfloat162 h0 = *(__nv_bfloat162*)&h.x, h1 = *(__nv_bfloat162*)&h.y;
    __nv_bfloat162 l0 = *(__nv_bfloat162*)&l.x, l1 = *(__nv_bfloat162*)&l.y;
    float a = __bfloat162float(h0.x) + __bfloat162float(l0.x);
    float b = __bfloat162float(h0.y) + __bfloat162float(l0.y);
    float c = __bfloat162float(h1.x) + __bfloat162float(l1.x);
    float d = __bfloat162float(h1.y) + __bfloat162float(l1.y);
    float s = warp_sum(a*a + b*b + c*c + d*d);
    __shared__ float red[8];
    if ((tid & 31) == 0) red[tid >> 5] = s;
    __syncthreads();
    if (tid == 0) {
        float t = 0.0f;
#pragma unroll
        for (int i = 0; i < 8; i++) t += red[i];
        float tv = hbar[0] / (sqrtf(t) + 1e-8f);
        temp[row] = fminf(fmaxf(tv, 0.1f), 5.0f);
    }
}

__global__ void softmax_kernel(const float* __restrict__ sc, __nv_bfloat16* __restrict__ ahi,
                               __nv_bfloat16* __restrict__ alo)
{
    size_t row = blockIdx.x;
    const float* p = sc + row * (size_t)TT;
    int tid = threadIdx.x;
    const int base = tid * 8;

    float v[8];
    float4 a0 = *(const float4*)(p + base);
    float4 a1 = *(const float4*)(p + base + 4);
    v[0]=a0.x; v[1]=a0.y; v[2]=a0.z; v[3]=a0.w;
    v[4]=a1.x; v[5]=a1.y; v[6]=a1.z; v[7]=a1.w;

    float mx = v[0];
#pragma unroll
    for (int j = 1; j < 8; j++) mx = fmaxf(mx, v[j]);
    mx = warp_max(mx);
    __shared__ float red[8];
    __shared__ float bval;
    if ((tid & 31) == 0) red[tid >> 5] = mx;
    __syncthreads();
    if (tid == 0) {
        float m = red[0];
#pragma unroll
        for (int i = 1; i < 8; i++) m = fmaxf(m, red[i]);
        bval = m;
    }
    __syncthreads();
    mx = bval;
    float s = 0.0f;
#pragma unroll
    for (int j = 0; j < 8; j++) { v[j] = __expf(v[j] - mx); s += v[j]; }
    s = warp_sum(s);
    __syncthreads();
    if ((tid & 31) == 0) red[tid >> 5] = s;
    __syncthreads();
    if (tid == 0) {
        float t = 0.0f;
#pragma unroll
        for (int i = 0; i < 8; i++) t += red[i];
        bval = t;
    }
    __syncthreads();
    float inv = 1.0f / bval;

    uint32_t hp[4], lp[4];
#pragma unroll
    for (int q = 0; q < 4; q++) {
        __nv_bfloat16 h0, l0, h1, l1;
        split1(v[q*2]   * inv, h0, l0);
        split1(v[q*2+1] * inv, h1, l1);
        hp[q] = pack2(h0, h1);
        lp[q] = pack2(l0, l1);
    }
    size_t idx = row * (size_t)TT + base;
    *(uint4*)(ahi + idx) = make_uint4(hp[0], hp[1], hp[2], hp[3]);
    *(uint4*)(alo + idx) = make_uint4(lp[0], lp[1], lp[2], lp[3]);
}

// ---------------------------------------------------------------------------
extern "C" void kernel_launch(void* const* d_in, const int* in_sizes, int n_in,
                              void* d_out, int out_size)
{
    const float* x  = (const float*)d_in[0];
    const float* Wq = (const float*)d_in[1];
    const float* Wk = (const float*)d_in[2];
    const float* Wv = (const float*)d_in[3];
    const float* hb = (const float*)d_in[4];
    float* out = (float*)d_out;

    __nv_bfloat16 *xhi,*xlo,*wqh,*wql,*wkh,*wkl,*wvh,*wvl,*qhi,*qlo,*khi,*klo,*vth,*vtl,*ahi,*alo;
    float *sc, *tmp;
    cudaGetSymbolAddress((void**)&xhi, g_xhi);  cudaGetSymbolAddress((void**)&xlo, g_xlo);
    cudaGetSymbolAddress((void**)&wqh, g_wqhi); cudaGetSymbolAddress((void**)&wql, g_wqlo);
    cudaGetSymbolAddress((void**)&wkh, g_wkhi); cudaGetSymbolAddress((void**)&wkl, g_wklo);
    cudaGetSymbolAddress((void**)&wvh, g_wvhi); cudaGetSymbolAddress((void**)&wvl, g_wvlo);
    cudaGetSymbolAddress((void**)&qhi, g_qhi);  cudaGetSymbolAddress((void**)&qlo, g_qlo);
    cudaGetSymbolAddress((void**)&khi, g_khi);  cudaGetSymbolAddress((void**)&klo, g_klo);
    cudaGetSymbolAddress((void**)&vth, g_vthi); cudaGetSymbolAddress((void**)&vtl, g_vtlo);
    cudaGetSymbolAddress((void**)&ahi, g_ahi);  cudaGetSymbolAddress((void**)&alo, g_alo);
    cudaGetSymbolAddress((void**)&sc,  g_sc);   cudaGetSymbolAddress((void**)&tmp, g_temp);

    cudaFuncSetAttribute(qkv_kernel,         cudaFuncAttributeMaxDynamicSharedMemorySize, SMEMSZ(8));
    cudaFuncSetAttribute((gemm3_kernel<2,8>), cudaFuncAttributeMaxDynamicSharedMemorySize, SMEMSZ(8));
    cudaFuncSetAttribute((gemm3_kernel<3,4>), cudaFuncAttributeMaxDynamicSharedMemorySize, SMEMSZ(4));

    // 1) splits: x + merged W
    split_kernel<<<(size_t)MTOT*DD/4/256, 256>>>(x, xhi, xlo, (size_t)MTOT*DD/4);
    {
        dim3 gw(DD*DD/4/256, 3);
        splitW_kernel<<<gw, 256>>>(Wq, Wk, Wv, wqh, wql, wkh, wkl, wvh, wvl);
    }

    // 2) merged q/k/v projections (BN=128)
    dim3 gq(DD/128, MTOT/BM, 3);
    qkv_kernel<<<gq, NTHR, SMEMSZ(8)>>>(xhi, xlo, wqh, wql, wkh, wkl, wvh, wvl,
                                        qhi, qlo, khi, klo, vth, vtl);

    // 3) temp
    temp_kernel<<<MTOT, 256>>>(qhi, qlo, hb, tmp);

    // 4) scores = (q@k^T) * temp   (BN=128)
    dim3 gs(TT/128, TT/BM, NB);
    gemm3_kernel<2,8><<<gs, NTHR, SMEMSZ(8)>>>(qhi, qlo, khi, klo, sc,
                                               DD, DD, DD, TT,
                                               (size_t)TT*DD, (size_t)TT*DD, (size_t)TT*TT, tmp);

    // 5) softmax -> attn hi/lo
    softmax_kernel<<<MTOT, 256>>>(sc, ahi, alo);

    // 6) out = attn @ v   (BN=64 -> 2048 tiles, kills the 4-wave tail)
    dim3 go(DD/64, TT/BM, NB);
    gemm3_kernel<3,4><<<go, NTHR, SMEMSZ(4)>>>(ahi, alo, vth, vtl, out,
                                               TT, TT, MTOT, DD,
                                               (size_t)TT*TT, TT, (size_t)TT*DD, nullptr);
}